// round 2
// baseline (speedup 1.0000x reference)
#include <cuda_runtime.h>
#include <math.h>

#define Bc 2
#define Sc 2048
#define Ec 1024
#define NHc 4
#define DHc 256

typedef unsigned long long ull;

// scratch (device globals: no allocation allowed)
__device__ float g_ig [Bc*NHc*Sc];
__device__ float g_lsf[Bc*NHc*Sc];
__device__ float g_m  [Bc*NHc*Sc];
__device__ float g_pm [Bc*NHc*Sc];
__device__ float g_mld[Bc*NHc*Sc];

// ---------------- f32x2 helpers ----------------
__device__ __forceinline__ void ffma2(ull &d, ull a, ull b) {
    asm("fma.rn.f32x2 %0, %1, %2, %0;" : "+l"(d) : "l"(a), "l"(b));
}
__device__ __forceinline__ ull pk2(float x, float y) {
    ull r; asm("mov.b64 %0, {%1, %2};" : "=l"(r) : "f"(x), "f"(y)); return r;
}
__device__ __forceinline__ float2 upk2(ull a) {
    float2 f; asm("mov.b64 {%0, %1}, %2;" : "=f"(f.x), "=f"(f.y) : "l"(a)); return f;
}

// ---------------------------------------------------------------------------
// Kernel A: gate pre-activations. One warp handles 4 rows, sharing weight loads
// (cuts L2 weight traffic 4x vs one-row-per-warp).
// ---------------------------------------------------------------------------
__global__ __launch_bounds__(256) void gates_kernel(
    const float* __restrict__ q, const float* __restrict__ k, const float* __restrict__ v,
    const float* __restrict__ igw, const float* __restrict__ igb,
    const float* __restrict__ fgw, const float* __restrict__ fgb)
{
    int warp = blockIdx.x * 8 + (threadIdx.x >> 5);
    int lane = threadIdx.x & 31;
    int row0 = warp * 4;

    float aig[4][4] = {{0}}, afg[4][4] = {{0}};

    #pragma unroll
    for (int part = 0; part < 3; ++part) {
        const float* bp = (part == 0) ? q : (part == 1) ? k : v;
        #pragma unroll
        for (int it = 0; it < 8; ++it) {
            int f  = it * 128 + lane * 4;
            int wf = part * 1024 + f;
            float4 wi[4], wg[4];
            #pragma unroll
            for (int h = 0; h < 4; ++h) {
                wi[h] = *(const float4*)(igw + h * 3072 + wf);
                wg[h] = *(const float4*)(fgw + h * 3072 + wf);
            }
            #pragma unroll
            for (int r = 0; r < 4; ++r) {
                float4 x = *(const float4*)(bp + (size_t)(row0 + r) * Ec + f);
                #pragma unroll
                for (int h = 0; h < 4; ++h) {
                    aig[r][h] += x.x*wi[h].x + x.y*wi[h].y + x.z*wi[h].z + x.w*wi[h].w;
                    afg[r][h] += x.x*wg[h].x + x.y*wg[h].y + x.z*wg[h].z + x.w*wg[h].w;
                }
            }
        }
    }
    #pragma unroll
    for (int o = 16; o; o >>= 1) {
        #pragma unroll
        for (int r = 0; r < 4; ++r)
            #pragma unroll
            for (int h = 0; h < 4; ++h) {
                aig[r][h] += __shfl_xor_sync(0xffffffffu, aig[r][h], o);
                afg[r][h] += __shfl_xor_sync(0xffffffffu, afg[r][h], o);
            }
    }
    // lane = r*8 + c ; c<4 -> igate head c, c>=4 -> fgate head c-4
    int r = lane >> 3, c = lane & 7;
    float val = 0.f;
    #pragma unroll
    for (int rr = 0; rr < 4; ++rr)
        #pragma unroll
        for (int h = 0; h < 4; ++h) {
            if (rr == r && c == h)     val = aig[rr][h];
            if (rr == r && c == h + 4) val = afg[rr][h];
        }
    int row = row0 + r;
    int b = row >> 11;
    int s = row & (Sc - 1);
    if (c < 4) {
        g_ig[(b * NHc + c) * Sc + s] = val + igb[c];
    } else {
        int h = c - 4;
        float fgv = val + fgb[h];
        float lsf = fminf(fgv, 0.f) - log1pf(expf(-fabsf(fgv)));
        g_lsf[(b * NHc + h) * Sc + s] = lsf;
    }
}

// ---------------------------------------------------------------------------
// Kernel B: scans (unchanged)
// ---------------------------------------------------------------------------
__global__ __launch_bounds__(1024) void scan_kernel()
{
    __shared__ float s_a[2048];
    __shared__ float s_b[2048];
    __shared__ float s_cs[2048];

    int bh = blockIdx.x;
    int t  = threadIdx.x;
    const int base = bh * Sc;

    s_a[t]        = g_lsf[base + t];
    s_a[t + 1024] = g_lsf[base + t + 1024];
    __syncthreads();

    float* src = s_a; float* dst = s_b;
    for (int off = 1; off < 2048; off <<= 1) {
        #pragma unroll
        for (int u = 0; u < 2; ++u) {
            int i = t + (u << 10);
            float val = src[i];
            if (i >= off) val += src[i - off];
            dst[i] = val;
        }
        __syncthreads();
        float* tmp = src; src = dst; dst = tmp;
    }
    s_cs[t]        = src[t];
    s_cs[t + 1024] = src[t + 1024];
    __syncthreads();

    #pragma unroll
    for (int u = 0; u < 2; ++u) {
        int i = t + (u << 10);
        float m = g_ig[base + i] - (i > 0 ? s_cs[i - 1] : 0.f);
        g_m[base + i] = m;
        s_a[i] = m;
    }
    __syncthreads();

    src = s_a; dst = s_b;
    for (int off = 1; off < 2048; off <<= 1) {
        #pragma unroll
        for (int u = 0; u < 2; ++u) {
            int i = t + (u << 10);
            float val = src[i];
            if (i >= off) val = fmaxf(val, src[i - off]);
            dst[i] = val;
        }
        __syncthreads();
        float* tmp = src; src = dst; dst = tmp;
    }
    #pragma unroll
    for (int u = 0; u < 2; ++u) {
        int i = t + (u << 10);
        g_pm[base + i]  = src[i];
        g_mld[base + i] = s_cs[i] + src[i];
    }
}

// ---------------------------------------------------------------------------
// Kernel C: FFMA2 (fma.rn.f32x2) tiled causal attention.
//   Qs : transposed Q tile   [d*64 + r]      (reused as H[64x260] in epilogue)
//   Ksd: duplicated K chunk  [dd*128 + 2c]   value (k,k)
//   Psd: duplicated P tile   [r*130 + 2j]    value (p,p)
//   Vs2: interleaved V tile  [j*256 + m*64 + 2l] = (V[j][64m+l], V[j][64m+32+l])
// ---------------------------------------------------------------------------
#define SM_QS   0
#define SM_KS   16640
#define SM_PS   (16640 + 8192)
#define SM_VS   (16640 + 8192 + 8320)
#define SM_RS   (16640 + 8192 + 8320 + 16384)
#define SM_FLOATS (SM_RS + 192)
#define SMEM_BYTES (SM_FLOATS * 4)

__global__ __launch_bounds__(256, 1) void attn_kernel(
    const float* __restrict__ q, const float* __restrict__ k,
    const float* __restrict__ v, const float* __restrict__ out_w,
    float* __restrict__ out)
{
    extern __shared__ float sm[];
    float* Qs     = sm + SM_QS;
    float* Ksd    = sm + SM_KS;
    float* Psd    = sm + SM_PS;
    float* Vs2    = sm + SM_VS;
    float* rowsum = sm + SM_RS;   // [64]
    float* rowpm  = rowsum + 64;  // [64]
    float* rowmld = rowpm + 64;   // [64]

    const int tid  = threadIdx.x;
    const int bh   = blockIdx.x >> 4;
    const int pair = blockIdx.x & 15;
    const int b = bh >> 2, h = bh & 3;

    const size_t hb = (size_t)h * DHc;
    const float* qB = q + (size_t)b * Sc * Ec + hb;
    const float* kB = k + (size_t)b * Sc * Ec + hb;
    const float* vB = v + (size_t)b * Sc * Ec + hb;
    const float* mArr = g_m + bh * Sc;

    const int ty  = tid >> 4, tx  = tid & 15;   // QK: 16x16 threads, 4x4 micro-tile
    const int ty2 = tid >> 5, tx2 = tid & 31;   // PV: 8x32 threads

    for (int which = 0; which < 2; ++which) {
        const int rt = which ? (31 - pair) : pair;
        const int r0 = rt * 64;

        // ---- load Q tile transposed: Qs[d][r] ----
        {
            int r  = tid & 63;
            int dq = (tid >> 6) << 6;
            const float* src = qB + (size_t)(r0 + r) * Ec + dq;
            #pragma unroll
            for (int i = 0; i < 16; ++i) {
                float4 x = *(const float4*)(src + i * 4);
                int d = dq + i * 4;
                Qs[(d+0)*64 + r] = x.x;
                Qs[(d+1)*64 + r] = x.y;
                Qs[(d+2)*64 + r] = x.z;
                Qs[(d+3)*64 + r] = x.w;
            }
            if (tid < 64) {
                rowsum[tid] = 0.f;
                rowpm [tid] = g_pm [bh * Sc + r0 + tid];
                rowmld[tid] = g_mld[bh * Sc + r0 + tid];
            }
        }

        ull o2[8][4];
        #pragma unroll
        for (int a = 0; a < 8; ++a)
            #pragma unroll
            for (int m = 0; m < 4; ++m) o2[a][m] = 0ull;

        __syncthreads();

        for (int jt = 0; jt <= rt; ++jt) {
            const int t0 = jt * 64;

            // ---------------- QK^T (f32x2) ----------------
            ull p2[2][4];
            #pragma unroll
            for (int i = 0; i < 2; ++i)
                #pragma unroll
                for (int j = 0; j < 4; ++j) p2[i][j] = 0ull;

            for (int ch = 0; ch < 4; ++ch) {
                { // load K chunk transposed + duplicated: Ksd[dd*128 + 2c] = (k,k)
                    int c  = tid & 63;
                    int db = (tid >> 6) << 4;
                    const float* src = kB + (size_t)(t0 + c) * Ec + ch * 64 + db;
                    #pragma unroll
                    for (int i = 0; i < 4; ++i) {
                        float4 x = *(const float4*)(src + i * 4);
                        int dd = db + i * 4;
                        *(ull*)(Ksd + (size_t)(dd+0)*128 + 2*c) = pk2(x.x, x.x);
                        *(ull*)(Ksd + (size_t)(dd+1)*128 + 2*c) = pk2(x.y, x.y);
                        *(ull*)(Ksd + (size_t)(dd+2)*128 + 2*c) = pk2(x.z, x.z);
                        *(ull*)(Ksd + (size_t)(dd+3)*128 + 2*c) = pk2(x.w, x.w);
                    }
                }
                __syncthreads();
                const float* Qc = Qs + (ch << 6) * 64;
                #pragma unroll 8
                for (int dd = 0; dd < 64; ++dd) {
                    ulonglong2 a = *(const ulonglong2*)(Qc + dd * 64 + 4 * ty);
                    ull b0 = *(const ull*)(Ksd + dd * 128 + 2 * (4 * tx + 0));
                    ull b1 = *(const ull*)(Ksd + dd * 128 + 2 * (4 * tx + 1));
                    ull b2 = *(const ull*)(Ksd + dd * 128 + 2 * (4 * tx + 2));
                    ull b3 = *(const ull*)(Ksd + dd * 128 + 2 * (4 * tx + 3));
                    ffma2(p2[0][0], a.x, b0); ffma2(p2[0][1], a.x, b1);
                    ffma2(p2[0][2], a.x, b2); ffma2(p2[0][3], a.x, b3);
                    ffma2(p2[1][0], a.y, b0); ffma2(p2[1][1], a.y, b1);
                    ffma2(p2[1][2], a.y, b2); ffma2(p2[1][3], a.y, b3);
                }
                __syncthreads();
            }

            // -------- decay * mask + row sums + store duplicated P --------
            {
                float p[4][4];
                #pragma unroll
                for (int ri = 0; ri < 2; ++ri)
                    #pragma unroll
                    for (int j = 0; j < 4; ++j) {
                        float2 f = upk2(p2[ri][j]);
                        p[2*ri  ][j] = f.x;
                        p[2*ri+1][j] = f.y;
                    }

                float mj[4];
                #pragma unroll
                for (int j = 0; j < 4; ++j) mj[j] = mArr[t0 + 4 * tx + j];

                float rsum[4];
                #pragma unroll
                for (int i = 0; i < 4; ++i) {
                    int gr = r0 + 4 * ty + i;
                    float pmv = rowpm[4 * ty + i];
                    float rs = 0.f;
                    #pragma unroll
                    for (int j = 0; j < 4; ++j) {
                        int gc = t0 + 4 * tx + j;
                        float val = (gc <= gr) ? p[i][j] * 0.0625f * __expf(mj[j] - pmv) : 0.f;
                        p[i][j] = val;
                        rs += val;
                    }
                    rsum[i] = rs;
                }
                #pragma unroll
                for (int off = 8; off; off >>= 1) {
                    #pragma unroll
                    for (int i = 0; i < 4; ++i)
                        rsum[i] += __shfl_xor_sync(0xffffffffu, rsum[i], off);
                }
                if (tx == 0) {
                    #pragma unroll
                    for (int i = 0; i < 4; ++i) rowsum[4 * ty + i] += rsum[i];
                }
                #pragma unroll
                for (int i = 0; i < 4; ++i)
                    #pragma unroll
                    for (int j = 0; j < 4; ++j)
                        *(ull*)(Psd + (size_t)(4*ty+i)*130 + 2*(4*tx+j)) = pk2(p[i][j], p[i][j]);
            }
            __syncthreads();

            // -------- load full V tile, interleaved pairs --------
            #pragma unroll
            for (int it = 0; it < 32; ++it) {
                int u = tid + it * 256;
                int j = u >> 7, rem = u & 127;
                int m = rem >> 5, l = rem & 31;
                const float* vp = vB + (size_t)(t0 + j) * Ec + 64 * m + l;
                float v0 = vp[0];
                float v1 = vp[32];
                float* d = Vs2 + j * 256 + m * 64 + 2 * l;
                d[0] = v0; d[1] = v1;
            }
            __syncthreads();

            // ---------------- P @ V (f32x2) ----------------
            #pragma unroll 4
            for (int j = 0; j < 64; ++j) {
                ull b0 = *(const ull*)(Vs2 + j * 256 +   0 + 2 * tx2);
                ull b1 = *(const ull*)(Vs2 + j * 256 +  64 + 2 * tx2);
                ull b2 = *(const ull*)(Vs2 + j * 256 + 128 + 2 * tx2);
                ull b3 = *(const ull*)(Vs2 + j * 256 + 192 + 2 * tx2);
                #pragma unroll
                for (int rr = 0; rr < 8; ++rr) {
                    ull a = *(const ull*)(Psd + (size_t)(ty2 + 8*rr) * 130 + 2 * j);
                    ffma2(o2[rr][0], a, b0);
                    ffma2(o2[rr][1], a, b1);
                    ffma2(o2[rr][2], a, b2);
                    ffma2(o2[rr][3], a, b3);
                }
            }
            __syncthreads();
        } // jt

        // ---------------- epilogue ----------------
        {
            float inv[8];
            #pragma unroll
            for (int rr = 0; rr < 8; ++rr) {
                int r = ty2 + 8 * rr;
                float nrm = fmaxf(fabsf(rowsum[r]), expf(-rowmld[r])) + 1e-8f;
                inv[rr] = 1.f / nrm;
            }
            #pragma unroll
            for (int rr = 0; rr < 8; ++rr) {
                int r = ty2 + 8 * rr;
                #pragma unroll
                for (int m = 0; m < 4; ++m) {
                    float2 f = upk2(o2[rr][m]);
                    Qs[r * 260 + 64 * m + tx2]      = f.x * inv[rr];
                    Qs[r * 260 + 64 * m + 32 + tx2] = f.y * inv[rr];
                }
            }
        }
        __syncthreads();
        {
            int r  = tid >> 2;
            int qd = tid & 3;
            const float* hrow = Qs + r * 260 + qd * 64;
            float s1 = 0.f;
            #pragma unroll
            for (int i = 0; i < 16; ++i) {
                float4 x = *(const float4*)(hrow + i * 4);
                s1 += x.x + x.y + x.z + x.w;
            }
            s1 += __shfl_xor_sync(0xffffffffu, s1, 1);
            s1 += __shfl_xor_sync(0xffffffffu, s1, 2);
            float mean = s1 * (1.f / 256.f);
            float s2 = 0.f;
            #pragma unroll
            for (int i = 0; i < 16; ++i) {
                float4 x = *(const float4*)(hrow + i * 4);
                float d0 = x.x - mean, d1 = x.y - mean, d2 = x.z - mean, d3 = x.w - mean;
                s2 += d0*d0 + d1*d1 + d2*d2 + d3*d3;
            }
            s2 += __shfl_xor_sync(0xffffffffu, s2, 1);
            s2 += __shfl_xor_sync(0xffffffffu, s2, 2);
            float rstd = rsqrtf(s2 * (1.f / 256.f) + 1e-5f);

            float* dst = out + ((size_t)b * Sc + r0 + r) * Ec + hb + qd * 64;
            const float* ow = out_w + hb + qd * 64;
            #pragma unroll
            for (int i = 0; i < 16; ++i) {
                float4 x = *(const float4*)(hrow + i * 4);
                float4 w = *(const float4*)(ow + i * 4);
                float4 y;
                y.x = (x.x - mean) * rstd * (1.f + w.x);
                y.y = (x.y - mean) * rstd * (1.f + w.y);
                y.z = (x.z - mean) * rstd * (1.f + w.z);
                y.w = (x.w - mean) * rstd * (1.f + w.w);
                *(float4*)(dst + i * 4) = y;
            }
        }
        __syncthreads();
    } // which
}

// ---------------------------------------------------------------------------
extern "C" void kernel_launch(void* const* d_in, const int* in_sizes, int n_in,
                              void* d_out, int out_size)
{
    const float* q   = (const float*)d_in[0];
    const float* k   = (const float*)d_in[1];
    const float* v   = (const float*)d_in[2];
    const float* igw = (const float*)d_in[3];
    const float* igb = (const float*)d_in[4];
    const float* fgw = (const float*)d_in[5];
    const float* fgb = (const float*)d_in[6];
    const float* ow  = (const float*)d_in[7];
    float* out = (float*)d_out;

    cudaFuncSetAttribute(attn_kernel, cudaFuncAttributeMaxDynamicSharedMemorySize, SMEM_BYTES);

    gates_kernel<<<(Bc * Sc) / 32, 256>>>(q, k, v, igw, igb, fgw, fgb);
    scan_kernel<<<Bc * NHc, 1024>>>();
    attn_kernel<<<(Bc * NHc) * 16, 256, SMEM_BYTES>>>(q, k, v, ow, out);
}

// round 4
// speedup vs baseline: 5.2919x; 5.2919x over previous
#include <cuda_runtime.h>
#include <cuda_fp16.h>
#include <math.h>
#include <stdint.h>

#define Bc 2
#define Sc 2048
#define Ec 1024
#define NHc 4
#define DHc 256
#define BH  8
#define KT  64
#define NRT 32

// ------------------------- device scratch -------------------------
__device__ float g_ig [BH*Sc];
__device__ float g_lsf[BH*Sc];
__device__ float g_m  [BH*Sc];
__device__ float g_pm [BH*Sc];
__device__ float g_mld[BH*Sc];
__device__ float g_ct [BH*NRT];
__device__ __half g_qh[(size_t)BH*Sc*DHc];
__device__ __half g_kh[(size_t)BH*Sc*DHc];
__device__ __half g_vh[(size_t)BH*Sc*DHc];

// ------------------------- helpers -------------------------
__device__ __forceinline__ uint32_t smem_u32(const void* p) {
    uint32_t a;
    asm("{ .reg .u64 t; cvta.to.shared.u64 t, %1; cvt.u32.u64 %0, t; }" : "=r"(a) : "l"(p));
    return a;
}
__device__ __forceinline__ void ldsm4(uint32_t* r, uint32_t a) {
    asm volatile("ldmatrix.sync.aligned.m8n8.x4.shared.b16 {%0,%1,%2,%3}, [%4];"
        : "=r"(r[0]), "=r"(r[1]), "=r"(r[2]), "=r"(r[3]) : "r"(a));
}
__device__ __forceinline__ void ldsm4t(uint32_t* r, uint32_t a) {
    asm volatile("ldmatrix.sync.aligned.m8n8.x4.trans.shared.b16 {%0,%1,%2,%3}, [%4];"
        : "=r"(r[0]), "=r"(r[1]), "=r"(r[2]), "=r"(r[3]) : "r"(a));
}
__device__ __forceinline__ void mma16816(float* c, const uint32_t* a, const uint32_t* b) {
    asm volatile("mma.sync.aligned.m16n8k16.row.col.f32.f16.f16.f32 "
        "{%0,%1,%2,%3}, {%4,%5,%6,%7}, {%8,%9}, {%0,%1,%2,%3};"
        : "+f"(c[0]), "+f"(c[1]), "+f"(c[2]), "+f"(c[3])
        : "r"(a[0]), "r"(a[1]), "r"(a[2]), "r"(a[3]), "r"(b[0]), "r"(b[1]));
}
__device__ __forceinline__ uint32_t pkh2(float lo, float hi) {
    uint32_t r; asm("cvt.rn.f16x2.f32 %0, %1, %2;" : "=r"(r) : "f"(hi), "f"(lo)); return r;
}

// ---------------------------------------------------------------------------
// gates: one warp per (b,s) row
// ---------------------------------------------------------------------------
__global__ __launch_bounds__(256) void gates_kernel(
    const float* __restrict__ q, const float* __restrict__ k, const float* __restrict__ v,
    const float* __restrict__ igw, const float* __restrict__ igb,
    const float* __restrict__ fgw, const float* __restrict__ fgb)
{
    int row  = blockIdx.x * 8 + (threadIdx.x >> 5);
    int lane = threadIdx.x & 31;
    int b = row >> 11;
    int s = row & (Sc - 1);
    size_t off = (size_t)row * Ec;

    float aig[4] = {0.f,0.f,0.f,0.f};
    float afg[4] = {0.f,0.f,0.f,0.f};

    #pragma unroll
    for (int part = 0; part < 3; ++part) {
        const float* bp = (part == 0) ? (q + off) : (part == 1) ? (k + off) : (v + off);
        #pragma unroll
        for (int it = 0; it < 8; ++it) {
            int f = it * 128 + lane * 4;
            float4 x = *(const float4*)(bp + f);
            int wf = part * 1024 + f;
            #pragma unroll
            for (int h = 0; h < 4; ++h) {
                float4 w = *(const float4*)(igw + h * 3072 + wf);
                aig[h] += x.x*w.x + x.y*w.y + x.z*w.z + x.w*w.w;
                float4 g = *(const float4*)(fgw + h * 3072 + wf);
                afg[h] += x.x*g.x + x.y*g.y + x.z*g.z + x.w*g.w;
            }
        }
    }
    #pragma unroll
    for (int o = 16; o; o >>= 1) {
        #pragma unroll
        for (int h = 0; h < 4; ++h) {
            aig[h] += __shfl_xor_sync(0xffffffffu, aig[h], o);
            afg[h] += __shfl_xor_sync(0xffffffffu, afg[h], o);
        }
    }
    if (lane < 4) {
        float val = (lane==0?aig[0]:lane==1?aig[1]:lane==2?aig[2]:aig[3]) + igb[lane];
        g_ig[(b * NHc + lane) * Sc + s] = val;
    } else if (lane < 8) {
        int h = lane - 4;
        float fgv = (h==0?afg[0]:h==1?afg[1]:h==2?afg[2]:afg[3]) + fgb[h];
        float lsf = fminf(fgv, 0.f) - log1pf(expf(-fabsf(fgv)));
        g_lsf[(b * NHc + h) * Sc + s] = lsf;
    }
}

// ---------------------------------------------------------------------------
// scan: cumsum, m, per-64-tile max, prefix-max, mld
// ---------------------------------------------------------------------------
__global__ __launch_bounds__(1024) void scan_kernel()
{
    __shared__ float s_a[2048];
    __shared__ float s_b[2048];
    __shared__ float s_cs[2048];

    int bh = blockIdx.x;
    int t  = threadIdx.x;
    const int base = bh * Sc;

    s_a[t]        = g_lsf[base + t];
    s_a[t + 1024] = g_lsf[base + t + 1024];
    __syncthreads();

    float* src = s_a; float* dst = s_b;
    for (int off = 1; off < 2048; off <<= 1) {
        #pragma unroll
        for (int u = 0; u < 2; ++u) {
            int i = t + (u << 10);
            float val = src[i];
            if (i >= off) val += src[i - off];
            dst[i] = val;
        }
        __syncthreads();
        float* tmp = src; src = dst; dst = tmp;
    }
    s_cs[t]        = src[t];
    s_cs[t + 1024] = src[t + 1024];
    __syncthreads();

    #pragma unroll
    for (int u = 0; u < 2; ++u) {
        int i = t + (u << 10);
        float m = g_ig[base + i] - (i > 0 ? s_cs[i - 1] : 0.f);
        g_m[base + i] = m;
        s_a[i] = m;
    }
    __syncthreads();

    if (t < NRT) {
        float mx = -1e30f;
        #pragma unroll 4
        for (int i = 0; i < KT; ++i) mx = fmaxf(mx, s_a[t * KT + i]);
        g_ct[bh * NRT + t] = mx;
    }
    __syncthreads();

    src = s_a; dst = s_b;
    for (int off = 1; off < 2048; off <<= 1) {
        #pragma unroll
        for (int u = 0; u < 2; ++u) {
            int i = t + (u << 10);
            float val = src[i];
            if (i >= off) val = fmaxf(val, src[i - off]);
            dst[i] = val;
        }
        __syncthreads();
        float* tmp = src; src = dst; dst = tmp;
    }
    #pragma unroll
    for (int u = 0; u < 2; ++u) {
        int i = t + (u << 10);
        g_pm[base + i]  = src[i];
        g_mld[base + i] = s_cs[i] + src[i];
    }
}

// ---------------------------------------------------------------------------
// prep: q,v -> fp16 ; k -> fp16 scaled by exp(m - ct)/16, head-split layout
// ---------------------------------------------------------------------------
__global__ __launch_bounds__(256) void prep_qkv(const float* __restrict__ q,
                                                const float* __restrict__ k,
                                                const float* __restrict__ v)
{
    int row = blockIdx.x;           // b*S + s
    int b = row >> 11, s = row & 2047;
    int t = threadIdx.x;
    int h = t >> 6;
    int d = (t & 63) * 4;
    int bh = b * NHc + h;
    float sc = __expf(g_m[bh * Sc + s] - g_ct[bh * NRT + (s >> 6)]) * 0.0625f;
    float4 qv = *(const float4*)(q + (size_t)row * Ec + t * 4);
    float4 kv = *(const float4*)(k + (size_t)row * Ec + t * 4);
    float4 vv = *(const float4*)(v + (size_t)row * Ec + t * 4);
    size_t o = ((size_t)bh * Sc + s) * DHc + d;
    __half2* qo = (__half2*)(g_qh + o);
    qo[0] = __floats2half2_rn(qv.x, qv.y);
    qo[1] = __floats2half2_rn(qv.z, qv.w);
    __half2* ko = (__half2*)(g_kh + o);
    ko[0] = __floats2half2_rn(kv.x * sc, kv.y * sc);
    ko[1] = __floats2half2_rn(kv.z * sc, kv.w * sc);
    __half2* vo = (__half2*)(g_vh + o);
    vo[0] = __floats2half2_rn(vv.x, vv.y);
    vo[1] = __floats2half2_rn(vv.z, vv.w);
}

// ---------------------------------------------------------------------------
// attention: HMMA mma.sync fp16, 128 blocks = bh x 16 paired 64-row tiles
// ---------------------------------------------------------------------------
#define OK_  0
#define OV_  33792
#define OPS  67584
#define ORS  76800
#define OINV 77312
#define OCT  77568
#define SMEM_BYTES 77696

__global__ __launch_bounds__(256, 1) void attn_kernel(
    const float* __restrict__ out_w, float* __restrict__ out)
{
    extern __shared__ char smb[];
    const uint32_t sb = smem_u32(smb);

    float* rsA  = (float*)(smb + ORS);
    float* sinv = (float*)(smb + OINV);
    float* sct  = (float*)(smb + OCT);

    const int tid  = threadIdx.x;
    const int wid  = tid >> 5;
    const int lane = tid & 31;
    const int bh   = blockIdx.x >> 4;
    const int pair = blockIdx.x & 15;
    const int b = bh >> 2, h = bh & 3;

    const int wm = wid & 3;        // m-tile (16 rows)
    const int wn = wid >> 2;       // key half (QK) / dh half (PV)
    const int m0 = wm * 16;
    const int g  = lane >> 2;
    const int tg = lane & 3;

    if (tid < NRT) sct[tid] = g_ct[bh * NRT + tid];

    const __half* qG = g_qh + (size_t)bh * Sc * DHc;
    const __half* kG = g_kh + (size_t)bh * Sc * DHc;
    const __half* vG = g_vh + (size_t)bh * Sc * DHc;

    // per-thread ldmatrix address components
    const int lrow8  = (lane & 7) + 8 * ((lane >> 3) & 1);  // row pattern for A/V x4
    const int lcol8  = (lane >> 4);                          // col-quarter for A/V x4
    const int brow   = 32 * wn + (lane & 7);                 // K rows for B x4
    const int bq8    = (lane >> 3);                          // dh quarter 0..3

    for (int which = 0; which < 2; ++which) {
        const int rt = which ? (31 - pair) : pair;
        const int r0 = rt * KT;

        __syncthreads();
        // ---- stage Q tile into K region, then ldmatrix into registers
        {
            const __half* qsrc = qG + (size_t)r0 * DHc;
            #pragma unroll
            for (int it = 0; it < 8; ++it) {
                int lin = tid + it * 256;
                int row = lin >> 5, dh = (lin & 31) * 8;
                *(uint4*)(smb + OK_ + (row * 264 + dh) * 2) = *(const uint4*)(qsrc + (size_t)row * DHc + dh);
            }
        }
        __syncthreads();

        uint32_t qa[64];
        {
            uint32_t base = sb + OK_ + ((uint32_t)(m0 + lrow8) * 264 + (uint32_t)lcol8 * 8) * 2;
            #pragma unroll
            for (int ks = 0; ks < 16; ++ks) ldsm4(qa + 4 * ks, base + ks * 32);
        }

        const float pm_g  = g_pm[bh * Sc + r0 + m0 + g];
        const float pm_g8 = g_pm[bh * Sc + r0 + m0 + g + 8];
        float rs0 = 0.f, rs1 = 0.f;
        float o_[64];
        #pragma unroll
        for (int i = 0; i < 64; ++i) o_[i] = 0.f;

        for (int jt = 0; jt <= rt; ++jt) {
            const int t0 = jt * KT;

            __syncthreads();   // prev PV reads done; Q ldmatrix done (jt==0)
            {
                const __half* ksrc = kG + (size_t)t0 * DHc;
                const __half* vsrc = vG + (size_t)t0 * DHc;
                #pragma unroll
                for (int it = 0; it < 8; ++it) {
                    int lin = tid + it * 256;
                    int row = lin >> 5, dh = (lin & 31) * 8;
                    *(uint4*)(smb + OK_ + (row * 264 + dh) * 2) = *(const uint4*)(ksrc + (size_t)row * DHc + dh);
                    *(uint4*)(smb + OV_ + (row * 264 + dh) * 2) = *(const uint4*)(vsrc + (size_t)row * DHc + dh);
                }
            }
            __syncthreads();

            // ---------------- QK^T ----------------
            float c[16];
            #pragma unroll
            for (int i = 0; i < 16; ++i) c[i] = 0.f;

            {
                uint32_t kbase = sb + OK_ + ((uint32_t)brow * 264 + (uint32_t)bq8 * 8) * 2;
                #pragma unroll
                for (int ks2 = 0; ks2 < 8; ++ks2) {
                    #pragma unroll
                    for (int nt = 0; nt < 4; ++nt) {
                        uint32_t bb[4];
                        ldsm4(bb, kbase + (uint32_t)nt * (8 * 264 * 2) + (uint32_t)ks2 * 64);
                        mma16816(c + 4 * nt, qa + 8 * ks2,     bb);
                        mma16816(c + 4 * nt, qa + 8 * ks2 + 4, bb + 2);
                    }
                }
            }

            // ---------------- scale/mask/pack P, rowsum ----------------
            {
                float ag  = __expf(sct[jt] - pm_g);
                float ag8 = __expf(sct[jt] - pm_g8);
                bool diag = (jt == rt);
                int rowg = r0 + m0 + g;
                #pragma unroll
                for (int nt = 0; nt < 4; ++nt) {
                    int col = t0 + 32 * wn + nt * 8 + 2 * tg;
                    float v0 = c[4*nt+0] * ag;
                    float v1 = c[4*nt+1] * ag;
                    float v2 = c[4*nt+2] * ag8;
                    float v3 = c[4*nt+3] * ag8;
                    if (diag) {
                        if (col     > rowg)     v0 = 0.f;
                        if (col + 1 > rowg)     v1 = 0.f;
                        if (col     > rowg + 8) v2 = 0.f;
                        if (col + 1 > rowg + 8) v3 = 0.f;
                    }
                    rs0 += v0 + v1;
                    rs1 += v2 + v3;
                    int cl = 32 * wn + nt * 8 + 2 * tg;
                    *(uint32_t*)(smb + OPS + ((m0 + g)     * 72 + cl) * 2) = pkh2(v0, v1);
                    *(uint32_t*)(smb + OPS + ((m0 + g + 8) * 72 + cl) * 2) = pkh2(v2, v3);
                }
            }
            __syncthreads();

            // ---------------- P @ V ----------------
            {
                uint32_t pabase = sb + OPS + ((uint32_t)(m0 + lrow8) * 72 + (uint32_t)lcol8 * 8) * 2;
                uint32_t vbase  = sb + OV_ + ((uint32_t)lrow8 * 264 + (uint32_t)(wn * 128) + (uint32_t)lcol8 * 8) * 2;
                #pragma unroll
                for (int kst = 0; kst < 4; ++kst) {
                    uint32_t pa[4];
                    ldsm4(pa, pabase + (uint32_t)kst * 32);
                    #pragma unroll
                    for (int ntp = 0; ntp < 8; ++ntp) {
                        uint32_t vb[4];
                        ldsm4t(vb, vbase + (uint32_t)kst * (16 * 264 * 2) + (uint32_t)ntp * 32);
                        mma16816(o_ + 4 * (2 * ntp),     pa, vb);
                        mma16816(o_ + 4 * (2 * ntp + 1), pa, vb + 2);
                    }
                }
            }
        } // jt

        // ---------------- rowsum reduce + normalizer ----------------
        rs0 += __shfl_xor_sync(0xffffffffu, rs0, 1);
        rs0 += __shfl_xor_sync(0xffffffffu, rs0, 2);
        rs1 += __shfl_xor_sync(0xffffffffu, rs1, 1);
        rs1 += __shfl_xor_sync(0xffffffffu, rs1, 2);
        __syncthreads();
        if (tg == 0) {
            rsA[wn * 64 + m0 + g]     = rs0;
            rsA[wn * 64 + m0 + g + 8] = rs1;
        }
        __syncthreads();
        if (tid < 64) {
            float s = rsA[tid] + rsA[64 + tid];
            float nrm = fmaxf(fabsf(s), __expf(-g_mld[bh * Sc + r0 + tid])) + 1e-8f;
            sinv[tid] = 1.f / nrm;
        }
        __syncthreads();

        // ---------------- O -> H staging (f32, stride 260) ----------------
        {
            float* H = (float*)smb;
            float ivg  = sinv[m0 + g];
            float ivg8 = sinv[m0 + g + 8];
            #pragma unroll
            for (int nt = 0; nt < 16; ++nt) {
                int col = wn * 128 + nt * 8 + 2 * tg;
                H[(m0 + g)     * 260 + col]     = o_[4*nt+0] * ivg;
                H[(m0 + g)     * 260 + col + 1] = o_[4*nt+1] * ivg;
                H[(m0 + g + 8) * 260 + col]     = o_[4*nt+2] * ivg8;
                H[(m0 + g + 8) * 260 + col + 1] = o_[4*nt+3] * ivg8;
            }
        }
        __syncthreads();

        // ---------------- LayerNorm + affine + store ----------------
        {
            const float* H = (const float*)smb;
            int r  = tid >> 2;
            int qd = tid & 3;
            const float* hrow = H + r * 260 + qd * 64;
            float s1 = 0.f;
            #pragma unroll
            for (int i = 0; i < 16; ++i) {
                float4 x = *(const float4*)(hrow + i * 4);
                s1 += x.x + x.y + x.z + x.w;
            }
            s1 += __shfl_xor_sync(0xffffffffu, s1, 1);
            s1 += __shfl_xor_sync(0xffffffffu, s1, 2);
            float mean = s1 * (1.f / 256.f);
            float s2 = 0.f;
            #pragma unroll
            for (int i = 0; i < 16; ++i) {
                float4 x = *(const float4*)(hrow + i * 4);
                float d0 = x.x - mean, d1 = x.y - mean, d2 = x.z - mean, d3 = x.w - mean;
                s2 += d0*d0 + d1*d1 + d2*d2 + d3*d3;
            }
            s2 += __shfl_xor_sync(0xffffffffu, s2, 1);
            s2 += __shfl_xor_sync(0xffffffffu, s2, 2);
            float rstd = rsqrtf(s2 * (1.f / 256.f) + 1e-5f);

            float* dst = out + ((size_t)b * Sc + r0 + r) * Ec + h * DHc + qd * 64;
            const float* ow = out_w + h * DHc + qd * 64;
            #pragma unroll
            for (int i = 0; i < 16; ++i) {
                float4 x = *(const float4*)(hrow + i * 4);
                float4 w = *(const float4*)(ow + i * 4);
                float4 y;
                y.x = (x.x - mean) * rstd * (1.f + w.x);
                y.y = (x.y - mean) * rstd * (1.f + w.y);
                y.z = (x.z - mean) * rstd * (1.f + w.z);
                y.w = (x.w - mean) * rstd * (1.f + w.w);
                *(float4*)(dst + i * 4) = y;
            }
        }
        __syncthreads();
    } // which
}

// ---------------------------------------------------------------------------
extern "C" void kernel_launch(void* const* d_in, const int* in_sizes, int n_in,
                              void* d_out, int out_size)
{
    const float* q   = (const float*)d_in[0];
    const float* k   = (const float*)d_in[1];
    const float* v   = (const float*)d_in[2];
    const float* igw = (const float*)d_in[3];
    const float* igb = (const float*)d_in[4];
    const float* fgw = (const float*)d_in[5];
    const float* fgb = (const float*)d_in[6];
    const float* ow  = (const float*)d_in[7];
    float* out = (float*)d_out;

    cudaFuncSetAttribute(attn_kernel, cudaFuncAttributeMaxDynamicSharedMemorySize, SMEM_BYTES);

    gates_kernel<<<(Bc * Sc) / 8, 256>>>(q, k, v, igw, igb, fgw, fgb);
    scan_kernel<<<BH, 1024>>>();
    prep_qkv<<<Bc * Sc, 256>>>(q, k, v);
    attn_kernel<<<BH * 16, 256, SMEM_BYTES>>>(ow, out);
}

// round 5
// speedup vs baseline: 8.3456x; 1.5771x over previous
#include <cuda_runtime.h>
#include <cuda_fp16.h>
#include <math.h>
#include <stdint.h>

#define Bc 2
#define Sc 2048
#define Ec 1024
#define NHc 4
#define DHc 256
#define BH  8
#define KT  64
#define NRT 32

// ------------------------- device scratch -------------------------
__device__ float g_ig [BH*Sc];
__device__ float g_lsf[BH*Sc];
__device__ float g_m  [BH*Sc];
__device__ float g_pm [BH*Sc];
__device__ float g_mld[BH*Sc];
__device__ float g_ct [BH*NRT];
__device__ __half g_qh[(size_t)BH*Sc*DHc];
__device__ __half g_kh[(size_t)BH*Sc*DHc];
__device__ __half g_vh[(size_t)BH*Sc*DHc];

// ------------------------- helpers -------------------------
__device__ __forceinline__ uint32_t smem_u32(const void* p) {
    uint32_t a;
    asm("{ .reg .u64 t; cvta.to.shared.u64 t, %1; cvt.u32.u64 %0, t; }" : "=r"(a) : "l"(p));
    return a;
}
__device__ __forceinline__ void ldsm4(uint32_t* r, uint32_t a) {
    asm volatile("ldmatrix.sync.aligned.m8n8.x4.shared.b16 {%0,%1,%2,%3}, [%4];"
        : "=r"(r[0]), "=r"(r[1]), "=r"(r[2]), "=r"(r[3]) : "r"(a));
}
__device__ __forceinline__ void ldsm4t(uint32_t* r, uint32_t a) {
    asm volatile("ldmatrix.sync.aligned.m8n8.x4.trans.shared.b16 {%0,%1,%2,%3}, [%4];"
        : "=r"(r[0]), "=r"(r[1]), "=r"(r[2]), "=r"(r[3]) : "r"(a));
}
__device__ __forceinline__ void mma16816(float* c, const uint32_t* a, const uint32_t* b) {
    asm volatile("mma.sync.aligned.m16n8k16.row.col.f32.f16.f16.f32 "
        "{%0,%1,%2,%3}, {%4,%5,%6,%7}, {%8,%9}, {%0,%1,%2,%3};"
        : "+f"(c[0]), "+f"(c[1]), "+f"(c[2]), "+f"(c[3])
        : "r"(a[0]), "r"(a[1]), "r"(a[2]), "r"(a[3]), "r"(b[0]), "r"(b[1]));
}
__device__ __forceinline__ uint32_t pkh2(float lo, float hi) {
    uint32_t r; asm("cvt.rn.f16x2.f32 %0, %1, %2;" : "=r"(r) : "f"(hi), "f"(lo)); return r;
}
__device__ __forceinline__ void cpa16(uint32_t s, const void* g) {
    asm volatile("cp.async.cg.shared.global [%0], [%1], 16;" :: "r"(s), "l"(g));
}
#define CP_COMMIT() asm volatile("cp.async.commit_group;" ::: "memory")
#define CP_WAIT0()  asm volatile("cp.async.wait_group 0;" ::: "memory")

// stage a 64x256-half tile into swizzled smem (512B rows, chunk^(row&7))
__device__ __forceinline__ void stage_tile(uint32_t dst, const __half* src, int tid) {
    #pragma unroll
    for (int it = 0; it < 8; ++it) {
        int lin = tid + it * 256;
        int row = lin >> 5, d8 = lin & 31;
        uint32_t o = dst + row * 512 + (uint32_t)((d8 ^ (row & 7)) << 4);
        cpa16(o, src + (size_t)row * 256 + d8 * 8);
    }
}

// ---------------------------------------------------------------------------
// gates: one warp per (b,s) row
// ---------------------------------------------------------------------------
__global__ __launch_bounds__(256) void gates_kernel(
    const float* __restrict__ q, const float* __restrict__ k, const float* __restrict__ v,
    const float* __restrict__ igw, const float* __restrict__ igb,
    const float* __restrict__ fgw, const float* __restrict__ fgb)
{
    int row  = blockIdx.x * 8 + (threadIdx.x >> 5);
    int lane = threadIdx.x & 31;
    int b = row >> 11;
    int s = row & (Sc - 1);
    size_t off = (size_t)row * Ec;

    float aig[4] = {0.f,0.f,0.f,0.f};
    float afg[4] = {0.f,0.f,0.f,0.f};

    #pragma unroll
    for (int part = 0; part < 3; ++part) {
        const float* bp = (part == 0) ? (q + off) : (part == 1) ? (k + off) : (v + off);
        #pragma unroll
        for (int it = 0; it < 8; ++it) {
            int f = it * 128 + lane * 4;
            float4 x = *(const float4*)(bp + f);
            int wf = part * 1024 + f;
            #pragma unroll
            for (int h = 0; h < 4; ++h) {
                float4 w = *(const float4*)(igw + h * 3072 + wf);
                aig[h] += x.x*w.x + x.y*w.y + x.z*w.z + x.w*w.w;
                float4 g = *(const float4*)(fgw + h * 3072 + wf);
                afg[h] += x.x*g.x + x.y*g.y + x.z*g.z + x.w*g.w;
            }
        }
    }
    #pragma unroll
    for (int o = 16; o; o >>= 1) {
        #pragma unroll
        for (int h = 0; h < 4; ++h) {
            aig[h] += __shfl_xor_sync(0xffffffffu, aig[h], o);
            afg[h] += __shfl_xor_sync(0xffffffffu, afg[h], o);
        }
    }
    if (lane < 4) {
        float val = (lane==0?aig[0]:lane==1?aig[1]:lane==2?aig[2]:aig[3]) + igb[lane];
        g_ig[(b * NHc + lane) * Sc + s] = val;
    } else if (lane < 8) {
        int h = lane - 4;
        float fgv = (h==0?afg[0]:h==1?afg[1]:h==2?afg[2]:afg[3]) + fgb[h];
        float lsf = fminf(fgv, 0.f) - log1pf(expf(-fabsf(fgv)));
        g_lsf[(b * NHc + h) * Sc + s] = lsf;
    }
}

// ---------------------------------------------------------------------------
// scan: cumsum, m, per-64-tile max, prefix-max, mld
// ---------------------------------------------------------------------------
__global__ __launch_bounds__(1024) void scan_kernel()
{
    __shared__ float s_a[2048];
    __shared__ float s_b[2048];
    __shared__ float s_cs[2048];

    int bh = blockIdx.x;
    int t  = threadIdx.x;
    const int base = bh * Sc;

    s_a[t]        = g_lsf[base + t];
    s_a[t + 1024] = g_lsf[base + t + 1024];
    __syncthreads();

    float* src = s_a; float* dst = s_b;
    for (int off = 1; off < 2048; off <<= 1) {
        #pragma unroll
        for (int u = 0; u < 2; ++u) {
            int i = t + (u << 10);
            float val = src[i];
            if (i >= off) val += src[i - off];
            dst[i] = val;
        }
        __syncthreads();
        float* tmp = src; src = dst; dst = tmp;
    }
    s_cs[t]        = src[t];
    s_cs[t + 1024] = src[t + 1024];
    __syncthreads();

    #pragma unroll
    for (int u = 0; u < 2; ++u) {
        int i = t + (u << 10);
        float m = g_ig[base + i] - (i > 0 ? s_cs[i - 1] : 0.f);
        g_m[base + i] = m;
        s_a[i] = m;
    }
    __syncthreads();

    if (t < NRT) {
        float mx = -1e30f;
        #pragma unroll 4
        for (int i = 0; i < KT; ++i) mx = fmaxf(mx, s_a[t * KT + i]);
        g_ct[bh * NRT + t] = mx;
    }
    __syncthreads();

    src = s_a; dst = s_b;
    for (int off = 1; off < 2048; off <<= 1) {
        #pragma unroll
        for (int u = 0; u < 2; ++u) {
            int i = t + (u << 10);
            float val = src[i];
            if (i >= off) val = fmaxf(val, src[i - off]);
            dst[i] = val;
        }
        __syncthreads();
        float* tmp = src; src = dst; dst = tmp;
    }
    #pragma unroll
    for (int u = 0; u < 2; ++u) {
        int i = t + (u << 10);
        g_pm[base + i]  = src[i];
        g_mld[base + i] = s_cs[i] + src[i];
    }
}

// ---------------------------------------------------------------------------
// prep: q,v -> fp16 ; k -> fp16 scaled by exp(m - ct)/16, head-split layout
// ---------------------------------------------------------------------------
__global__ __launch_bounds__(256) void prep_qkv(const float* __restrict__ q,
                                                const float* __restrict__ k,
                                                const float* __restrict__ v)
{
    int row = blockIdx.x;           // b*S + s
    int b = row >> 11, s = row & 2047;
    int t = threadIdx.x;
    int h = t >> 6;
    int d = (t & 63) * 4;
    int bh = b * NHc + h;
    float sc = __expf(g_m[bh * Sc + s] - g_ct[bh * NRT + (s >> 6)]) * 0.0625f;
    float4 qv = *(const float4*)(q + (size_t)row * Ec + t * 4);
    float4 kv = *(const float4*)(k + (size_t)row * Ec + t * 4);
    float4 vv = *(const float4*)(v + (size_t)row * Ec + t * 4);
    size_t o = ((size_t)bh * Sc + s) * DHc + d;
    __half2* qo = (__half2*)(g_qh + o);
    qo[0] = __floats2half2_rn(qv.x, qv.y);
    qo[1] = __floats2half2_rn(qv.z, qv.w);
    __half2* ko = (__half2*)(g_kh + o);
    ko[0] = __floats2half2_rn(kv.x * sc, kv.y * sc);
    ko[1] = __floats2half2_rn(kv.z * sc, kv.w * sc);
    __half2* vo = (__half2*)(g_vh + o);
    vo[0] = __floats2half2_rn(vv.x, vv.y);
    vo[1] = __floats2half2_rn(vv.z, vv.w);
}

// ---------------------------------------------------------------------------
// attention: HMMA + cp.async double-buffered K/V, swizzled smem
// ---------------------------------------------------------------------------
#define OQ_  0
#define OK0  32768
#define OK1  65536
#define OV0  98304
#define OV1  131072
#define OPS  163840
#define ORS  173056
#define OINV 173568
#define OCT  173824
#define SMEM_BYTES 174080

__global__ __launch_bounds__(256, 1) void attn_kernel(
    const float* __restrict__ out_w, float* __restrict__ out)
{
    extern __shared__ char smb[];
    const uint32_t sb = smem_u32(smb);

    float* rsA  = (float*)(smb + ORS);
    float* sinv = (float*)(smb + OINV);
    float* sct  = (float*)(smb + OCT);

    const int tid  = threadIdx.x;
    const int wid  = tid >> 5;
    const int lane = tid & 31;
    const int bh   = blockIdx.x >> 4;
    const int pair = blockIdx.x & 15;
    const int b = bh >> 2, h = bh & 3;

    const int wm = wid & 3;        // m-tile (16 rows)
    const int wn = wid >> 2;       // key half (QK) / dh half (PV)
    const int m0 = wm * 16;
    const int g  = lane >> 2;
    const int tg = lane & 3;
    const int s7 = lane & 7;       // swizzle key for all ldsm

    if (tid < NRT) sct[tid] = g_ct[bh * NRT + tid];

    const __half* qG = g_qh + (size_t)bh * Sc * DHc;
    const __half* kG = g_kh + (size_t)bh * Sc * DHc;
    const __half* vG = g_vh + (size_t)bh * Sc * DHc;

    const int lrow8 = (lane & 7) + 8 * ((lane >> 3) & 1);  // A/V row pattern
    const int lcol8 = (lane >> 4);                          // A/V col-quarter
    const int bq8   = (lane >> 3);                          // K dh quarter

    for (int which = 0; which < 2; ++which) {
        const int rt = which ? (31 - pair) : pair;
        const int r0 = rt * KT;

        __syncthreads();   // previous users of all smem done
        stage_tile(sb + OQ_, qG + (size_t)r0 * DHc, tid);
        stage_tile(sb + OK0, kG, tid);
        stage_tile(sb + OV0, vG, tid);
        CP_COMMIT();

        const float pm_g  = g_pm[bh * Sc + r0 + m0 + g];
        const float pm_g8 = g_pm[bh * Sc + r0 + m0 + g + 8];
        float rs0 = 0.f, rs1 = 0.f;
        float o_[64];
        #pragma unroll
        for (int i = 0; i < 64; ++i) o_[i] = 0.f;
        uint32_t qa[64];

        for (int jt = 0; jt <= rt; ++jt) {
            const int t0 = jt * KT;
            const uint32_t okb = sb + ((jt & 1) ? OK1 : OK0);
            const uint32_t ovb = sb + ((jt & 1) ? OV1 : OV0);

            CP_WAIT0();
            __syncthreads();

            // prefetch next tile (overlaps QK+epilogue+PV below)
            if (jt < rt) {
                stage_tile(sb + ((jt & 1) ? OK0 : OK1), kG + (size_t)(t0 + KT) * DHc, tid);
                stage_tile(sb + ((jt & 1) ? OV0 : OV1), vG + (size_t)(t0 + KT) * DHc, tid);
                CP_COMMIT();
            }

            if (jt == 0) {
                // load Q fragments (once per which)
                uint32_t rbase = sb + OQ_ + (uint32_t)(m0 + lrow8) * 512;
                #pragma unroll
                for (int ks = 0; ks < 16; ++ks)
                    ldsm4(qa + 4 * ks, rbase + (uint32_t)(((lcol8 + 2 * ks) ^ s7) << 4));
            }

            // ---------------- QK^T ----------------
            float c[16];
            #pragma unroll
            for (int i = 0; i < 16; ++i) c[i] = 0.f;
            {
                #pragma unroll
                for (int ks2 = 0; ks2 < 8; ++ks2) {
                    #pragma unroll
                    for (int nt = 0; nt < 4; ++nt) {
                        uint32_t bb[4];
                        uint32_t addr = okb + (uint32_t)(32 * wn + nt * 8 + s7) * 512
                                      + (uint32_t)((((ks2 << 2) + bq8) ^ s7) << 4);
                        ldsm4(bb, addr);
                        mma16816(c + 4 * nt, qa + 8 * ks2,     bb);
                        mma16816(c + 4 * nt, qa + 8 * ks2 + 4, bb + 2);
                    }
                }
            }

            // ---------------- scale/mask/pack P, rowsum ----------------
            {
                float ag  = __expf(sct[jt] - pm_g);
                float ag8 = __expf(sct[jt] - pm_g8);
                bool diag = (jt == rt);
                int rowg = r0 + m0 + g;
                #pragma unroll
                for (int nt = 0; nt < 4; ++nt) {
                    int col = t0 + 32 * wn + nt * 8 + 2 * tg;
                    float v0 = c[4*nt+0] * ag;
                    float v1 = c[4*nt+1] * ag;
                    float v2 = c[4*nt+2] * ag8;
                    float v3 = c[4*nt+3] * ag8;
                    if (diag) {
                        if (col     > rowg)     v0 = 0.f;
                        if (col + 1 > rowg)     v1 = 0.f;
                        if (col     > rowg + 8) v2 = 0.f;
                        if (col + 1 > rowg + 8) v3 = 0.f;
                    }
                    rs0 += v0 + v1;
                    rs1 += v2 + v3;
                    int cl = 32 * wn + nt * 8 + 2 * tg;
                    *(uint32_t*)(smb + OPS + ((m0 + g)     * 72 + cl) * 2) = pkh2(v0, v1);
                    *(uint32_t*)(smb + OPS + ((m0 + g + 8) * 72 + cl) * 2) = pkh2(v2, v3);
                }
            }
            __syncthreads();

            // ---------------- P @ V ----------------
            {
                uint32_t pabase = sb + OPS + ((uint32_t)(m0 + lrow8) * 72 + (uint32_t)lcol8 * 8) * 2;
                #pragma unroll
                for (int kst = 0; kst < 4; ++kst) {
                    uint32_t pa[4];
                    ldsm4(pa, pabase + (uint32_t)kst * 32);
                    uint32_t vrow = ovb + (uint32_t)(lrow8 + kst * 16) * 512;
                    #pragma unroll
                    for (int ntp = 0; ntp < 8; ++ntp) {
                        uint32_t vb[4];
                        ldsm4t(vb, vrow + (uint32_t)(((wn * 16 + ntp * 2 + lcol8) ^ s7) << 4));
                        mma16816(o_ + 4 * (2 * ntp),     pa, vb);
                        mma16816(o_ + 4 * (2 * ntp + 1), pa, vb + 2);
                    }
                }
            }
        } // jt

        // ---------------- rowsum reduce + normalizer ----------------
        rs0 += __shfl_xor_sync(0xffffffffu, rs0, 1);
        rs0 += __shfl_xor_sync(0xffffffffu, rs0, 2);
        rs1 += __shfl_xor_sync(0xffffffffu, rs1, 1);
        rs1 += __shfl_xor_sync(0xffffffffu, rs1, 2);
        __syncthreads();
        if (tg == 0) {
            rsA[wn * 64 + m0 + g]     = rs0;
            rsA[wn * 64 + m0 + g + 8] = rs1;
        }
        __syncthreads();
        if (tid < 64) {
            float s = rsA[tid] + rsA[64 + tid];
            float nrm = fmaxf(fabsf(s), __expf(-g_mld[bh * Sc + r0 + tid])) + 1e-8f;
            sinv[tid] = 1.f / nrm;
        }
        __syncthreads();

        // ---------------- O -> H staging (f32, stride 260) ----------------
        {
            float* H = (float*)smb;
            float ivg  = sinv[m0 + g];
            float ivg8 = sinv[m0 + g + 8];
            #pragma unroll
            for (int nt = 0; nt < 16; ++nt) {
                int col = wn * 128 + nt * 8 + 2 * tg;
                H[(m0 + g)     * 260 + col]     = o_[4*nt+0] * ivg;
                H[(m0 + g)     * 260 + col + 1] = o_[4*nt+1] * ivg;
                H[(m0 + g + 8) * 260 + col]     = o_[4*nt+2] * ivg8;
                H[(m0 + g + 8) * 260 + col + 1] = o_[4*nt+3] * ivg8;
            }
        }
        __syncthreads();

        // ---------------- LayerNorm + affine + store ----------------
        {
            const float* H = (const float*)smb;
            int r  = tid >> 2;
            int qd = tid & 3;
            const float* hrow = H + r * 260 + qd * 64;
            float s1 = 0.f;
            #pragma unroll
            for (int i = 0; i < 16; ++i) {
                float4 x = *(const float4*)(hrow + i * 4);
                s1 += x.x + x.y + x.z + x.w;
            }
            s1 += __shfl_xor_sync(0xffffffffu, s1, 1);
            s1 += __shfl_xor_sync(0xffffffffu, s1, 2);
            float mean = s1 * (1.f / 256.f);
            float s2 = 0.f;
            #pragma unroll
            for (int i = 0; i < 16; ++i) {
                float4 x = *(const float4*)(hrow + i * 4);
                float d0 = x.x - mean, d1 = x.y - mean, d2 = x.z - mean, d3 = x.w - mean;
                s2 += d0*d0 + d1*d1 + d2*d2 + d3*d3;
            }
            s2 += __shfl_xor_sync(0xffffffffu, s2, 1);
            s2 += __shfl_xor_sync(0xffffffffu, s2, 2);
            float rstd = rsqrtf(s2 * (1.f / 256.f) + 1e-5f);

            float* dst = out + ((size_t)b * Sc + r0 + r) * Ec + h * DHc + qd * 64;
            const float* ow = out_w + h * DHc + qd * 64;
            #pragma unroll
            for (int i = 0; i < 16; ++i) {
                float4 x = *(const float4*)(hrow + i * 4);
                float4 w = *(const float4*)(ow + i * 4);
                float4 y;
                y.x = (x.x - mean) * rstd * (1.f + w.x);
                y.y = (x.y - mean) * rstd * (1.f + w.y);
                y.z = (x.z - mean) * rstd * (1.f + w.z);
                y.w = (x.w - mean) * rstd * (1.f + w.w);
                *(float4*)(dst + i * 4) = y;
            }
        }
        __syncthreads();
    } // which
}

// ---------------------------------------------------------------------------
extern "C" void kernel_launch(void* const* d_in, const int* in_sizes, int n_in,
                              void* d_out, int out_size)
{
    const float* q   = (const float*)d_in[0];
    const float* k   = (const float*)d_in[1];
    const float* v   = (const float*)d_in[2];
    const float* igw = (const float*)d_in[3];
    const float* igb = (const float*)d_in[4];
    const float* fgw = (const float*)d_in[5];
    const float* fgb = (const float*)d_in[6];
    const float* ow  = (const float*)d_in[7];
    float* out = (float*)d_out;

    cudaFuncSetAttribute(attn_kernel, cudaFuncAttributeMaxDynamicSharedMemorySize, SMEM_BYTES);

    gates_kernel<<<(Bc * Sc) / 8, 256>>>(q, k, v, igw, igb, fgw, fgb);
    scan_kernel<<<BH, 1024>>>();
    prep_qkv<<<Bc * Sc, 256>>>(q, k, v);
    attn_kernel<<<BH * 16, 256, SMEM_BYTES>>>(ow, out);
}

// round 6
// speedup vs baseline: 8.8993x; 1.0663x over previous
#include <cuda_runtime.h>
#include <cuda_fp16.h>
#include <math.h>
#include <stdint.h>

#define Bc 2
#define Sc 2048
#define Ec 1024
#define NHc 4
#define DHc 256
#define BH  8
#define KT  64
#define NRT 32

// ------------------------- device scratch -------------------------
__device__ float g_ig [BH*Sc];
__device__ float g_lsf[BH*Sc];
__device__ float g_m  [BH*Sc];
__device__ float g_pm [BH*Sc];
__device__ float g_mld[BH*Sc];
__device__ float g_ct [BH*NRT];
__device__ __half g_qh[(size_t)BH*Sc*DHc];
__device__ __half g_kh[(size_t)BH*Sc*DHc];
__device__ __half g_vh[(size_t)BH*Sc*DHc];

// ------------------------- helpers -------------------------
__device__ __forceinline__ uint32_t smem_u32(const void* p) {
    uint32_t a;
    asm("{ .reg .u64 t; cvta.to.shared.u64 t, %1; cvt.u32.u64 %0, t; }" : "=r"(a) : "l"(p));
    return a;
}
__device__ __forceinline__ void ldsm4(uint32_t* r, uint32_t a) {
    asm volatile("ldmatrix.sync.aligned.m8n8.x4.shared.b16 {%0,%1,%2,%3}, [%4];"
        : "=r"(r[0]), "=r"(r[1]), "=r"(r[2]), "=r"(r[3]) : "r"(a));
}
__device__ __forceinline__ void ldsm4t(uint32_t* r, uint32_t a) {
    asm volatile("ldmatrix.sync.aligned.m8n8.x4.trans.shared.b16 {%0,%1,%2,%3}, [%4];"
        : "=r"(r[0]), "=r"(r[1]), "=r"(r[2]), "=r"(r[3]) : "r"(a));
}
__device__ __forceinline__ void mma16816(float* c, const uint32_t* a, const uint32_t* b) {
    asm volatile("mma.sync.aligned.m16n8k16.row.col.f32.f16.f16.f32 "
        "{%0,%1,%2,%3}, {%4,%5,%6,%7}, {%8,%9}, {%0,%1,%2,%3};"
        : "+f"(c[0]), "+f"(c[1]), "+f"(c[2]), "+f"(c[3])
        : "r"(a[0]), "r"(a[1]), "r"(a[2]), "r"(a[3]), "r"(b[0]), "r"(b[1]));
}
__device__ __forceinline__ uint32_t pkh2(float lo, float hi) {
    uint32_t r; asm("cvt.rn.f16x2.f32 %0, %1, %2;" : "=r"(r) : "f"(hi), "f"(lo)); return r;
}
__device__ __forceinline__ void cpa16(uint32_t s, const void* g) {
    asm volatile("cp.async.cg.shared.global [%0], [%1], 16;" :: "r"(s), "l"(g));
}
#define CP_COMMIT() asm volatile("cp.async.commit_group;" ::: "memory")
#define CP_WAIT0()  asm volatile("cp.async.wait_group 0;" ::: "memory")

// stage a 64x256-half tile into swizzled smem (512B rows, chunk^(row&7))
__device__ __forceinline__ void stage_tile(uint32_t dst, const __half* src, int tid) {
    #pragma unroll
    for (int it = 0; it < 8; ++it) {
        int lin = tid + it * 256;
        int row = lin >> 5, d8 = lin & 31;
        uint32_t o = dst + row * 512 + (uint32_t)((d8 ^ (row & 7)) << 4);
        cpa16(o, src + (size_t)row * 256 + d8 * 8);
    }
}

// ---------------------------------------------------------------------------
// gates: block caches all weights (96KB) in smem; 32 rows/block, 4 rows/warp
// ---------------------------------------------------------------------------
#define GATES_SMEM (24576 * 4)
__global__ __launch_bounds__(256) void gates_kernel(
    const float* __restrict__ q, const float* __restrict__ k, const float* __restrict__ v,
    const float* __restrict__ igw, const float* __restrict__ igb,
    const float* __restrict__ fgw, const float* __restrict__ fgb)
{
    extern __shared__ float ws[];   // [0:12288) igw, [12288:24576) fgw
    int tid  = threadIdx.x;
    int warp = tid >> 5;
    int lane = tid & 31;

    #pragma unroll
    for (int it = 0; it < 24; ++it) {
        int idx = tid + it * 256;   // float4 index 0..6143
        float4 val = (idx < 3072) ? ((const float4*)igw)[idx]
                                  : ((const float4*)fgw)[idx - 3072];
        ((float4*)ws)[idx] = val;
    }
    __syncthreads();

    int row0 = blockIdx.x * 32 + warp * 4;
    float acc[4][8];
    #pragma unroll
    for (int r = 0; r < 4; ++r)
        #pragma unroll
        for (int c = 0; c < 8; ++c) acc[r][c] = 0.f;

    #pragma unroll
    for (int part = 0; part < 3; ++part) {
        const float* bp = (part == 0) ? q : (part == 1) ? k : v;
        #pragma unroll
        for (int it = 0; it < 8; ++it) {
            int f  = it * 128 + lane * 4;
            int wf = part * 1024 + f;
            float4 wi[4], wg[4];
            #pragma unroll
            for (int h = 0; h < 4; ++h) {
                wi[h] = *(const float4*)(ws + h * 3072 + wf);
                wg[h] = *(const float4*)(ws + 12288 + h * 3072 + wf);
            }
            #pragma unroll
            for (int r = 0; r < 4; ++r) {
                float4 x = *(const float4*)(bp + (size_t)(row0 + r) * Ec + f);
                #pragma unroll
                for (int h = 0; h < 4; ++h) {
                    acc[r][h]     += x.x*wi[h].x + x.y*wi[h].y + x.z*wi[h].z + x.w*wi[h].w;
                    acc[r][h + 4] += x.x*wg[h].x + x.y*wg[h].y + x.z*wg[h].z + x.w*wg[h].w;
                }
            }
        }
    }
    #pragma unroll
    for (int o = 16; o; o >>= 1)
        #pragma unroll
        for (int r = 0; r < 4; ++r)
            #pragma unroll
            for (int c = 0; c < 8; ++c)
                acc[r][c] += __shfl_xor_sync(0xffffffffu, acc[r][c], o);

    int r = lane >> 3, c = lane & 7;
    float val = 0.f;
    #pragma unroll
    for (int rr = 0; rr < 4; ++rr)
        #pragma unroll
        for (int cc = 0; cc < 8; ++cc)
            if (rr == r && cc == c) val = acc[rr][cc];

    int row = row0 + r;
    int b = row >> 11;
    int s = row & (Sc - 1);
    if (c < 4) {
        g_ig[(b * NHc + c) * Sc + s] = val + igb[c];
    } else {
        int h = c - 4;
        float fgv = val + fgb[h];
        float lsf = fminf(fgv, 0.f) - log1pf(expf(-fabsf(fgv)));
        g_lsf[(b * NHc + h) * Sc + s] = lsf;
    }
}

// ---------------------------------------------------------------------------
// scan: cumsum, m, per-64-tile max, prefix-max, mld
// ---------------------------------------------------------------------------
__global__ __launch_bounds__(1024) void scan_kernel()
{
    __shared__ float s_a[2048];
    __shared__ float s_b[2048];
    __shared__ float s_cs[2048];

    int bh = blockIdx.x;
    int t  = threadIdx.x;
    const int base = bh * Sc;

    s_a[t]        = g_lsf[base + t];
    s_a[t + 1024] = g_lsf[base + t + 1024];
    __syncthreads();

    float* src = s_a; float* dst = s_b;
    for (int off = 1; off < 2048; off <<= 1) {
        #pragma unroll
        for (int u = 0; u < 2; ++u) {
            int i = t + (u << 10);
            float val = src[i];
            if (i >= off) val += src[i - off];
            dst[i] = val;
        }
        __syncthreads();
        float* tmp = src; src = dst; dst = tmp;
    }
    s_cs[t]        = src[t];
    s_cs[t + 1024] = src[t + 1024];
    __syncthreads();

    #pragma unroll
    for (int u = 0; u < 2; ++u) {
        int i = t + (u << 10);
        float m = g_ig[base + i] - (i > 0 ? s_cs[i - 1] : 0.f);
        g_m[base + i] = m;
        s_a[i] = m;
    }
    __syncthreads();

    if (t < NRT) {
        float mx = -1e30f;
        #pragma unroll 4
        for (int i = 0; i < KT; ++i) mx = fmaxf(mx, s_a[t * KT + i]);
        g_ct[bh * NRT + t] = mx;
    }
    __syncthreads();

    src = s_a; dst = s_b;
    for (int off = 1; off < 2048; off <<= 1) {
        #pragma unroll
        for (int u = 0; u < 2; ++u) {
            int i = t + (u << 10);
            float val = src[i];
            if (i >= off) val = fmaxf(val, src[i - off]);
            dst[i] = val;
        }
        __syncthreads();
        float* tmp = src; src = dst; dst = tmp;
    }
    #pragma unroll
    for (int u = 0; u < 2; ++u) {
        int i = t + (u << 10);
        g_pm[base + i]  = src[i];
        g_mld[base + i] = s_cs[i] + src[i];
    }
}

// ---------------------------------------------------------------------------
// prep: q,v -> fp16 ; k -> fp16 scaled by exp(m - ct)/16, head-split layout
// ---------------------------------------------------------------------------
__global__ __launch_bounds__(256) void prep_qkv(const float* __restrict__ q,
                                                const float* __restrict__ k,
                                                const float* __restrict__ v)
{
    int row = blockIdx.x;           // b*S + s
    int b = row >> 11, s = row & 2047;
    int t = threadIdx.x;
    int h = t >> 6;
    int d = (t & 63) * 4;
    int bh = b * NHc + h;
    float sc = __expf(g_m[bh * Sc + s] - g_ct[bh * NRT + (s >> 6)]) * 0.0625f;
    float4 qv = *(const float4*)(q + (size_t)row * Ec + t * 4);
    float4 kv = *(const float4*)(k + (size_t)row * Ec + t * 4);
    float4 vv = *(const float4*)(v + (size_t)row * Ec + t * 4);
    size_t o = ((size_t)bh * Sc + s) * DHc + d;
    __half2* qo = (__half2*)(g_qh + o);
    qo[0] = __floats2half2_rn(qv.x, qv.y);
    qo[1] = __floats2half2_rn(qv.z, qv.w);
    __half2* ko = (__half2*)(g_kh + o);
    ko[0] = __floats2half2_rn(kv.x * sc, kv.y * sc);
    ko[1] = __floats2half2_rn(kv.z * sc, kv.w * sc);
    __half2* vo = (__half2*)(g_vh + o);
    vo[0] = __floats2half2_rn(vv.x, vv.y);
    vo[1] = __floats2half2_rn(vv.z, vv.w);
}

// ---------------------------------------------------------------------------
// attention: HMMA, delayed-PV pipeline, K x2 / V x3 / P x2 buffers
// ---------------------------------------------------------------------------
#define OQ_  0
#define OK0  32768
#define OK1  65536
#define OV0  98304
#define OV1  131072
#define OV2  163840
#define OPS0 196608
#define OPS1 205824
#define ORS  215040
#define OINV 215552
#define OCT  215808
#define SMEM_BYTES 215936

__global__ __launch_bounds__(256, 1) void attn_kernel(
    const float* __restrict__ out_w, float* __restrict__ out)
{
    extern __shared__ char smb[];
    const uint32_t sb = smem_u32(smb);

    float* rsA  = (float*)(smb + ORS);
    float* sinv = (float*)(smb + OINV);
    float* sct  = (float*)(smb + OCT);

    const int tid  = threadIdx.x;
    const int wid  = tid >> 5;
    const int lane = tid & 31;
    const int bh   = blockIdx.x >> 4;
    const int pair = blockIdx.x & 15;
    const int b = bh >> 2, h = bh & 3;

    const int wm = wid & 3;        // m-tile (16 rows)
    const int wn = wid >> 2;       // key half (QK) / dh half (PV)
    const int m0 = wm * 16;
    const int g  = lane >> 2;
    const int tg = lane & 3;
    const int s7 = lane & 7;       // swizzle key

    if (tid < NRT) sct[tid] = g_ct[bh * NRT + tid];

    const __half* qG = g_qh + (size_t)bh * Sc * DHc;
    const __half* kG = g_kh + (size_t)bh * Sc * DHc;
    const __half* vG = g_vh + (size_t)bh * Sc * DHc;

    const int lrow8 = (lane & 7) + 8 * ((lane >> 3) & 1);  // A/V row pattern
    const int lcol8 = (lane >> 4);                          // A/V col-quarter
    const int bq8   = (lane >> 3);                          // K dh quarter

    const uint32_t vbuf[3] = { sb + OV0, sb + OV1, sb + OV2 };
    const uint32_t kbuf[2] = { sb + OK0, sb + OK1 };
    const uint32_t pbuf[2] = { sb + OPS0, sb + OPS1 };

    for (int which = 0; which < 2; ++which) {
        const int rt = which ? (31 - pair) : pair;
        const int r0 = rt * KT;

        __syncthreads();   // previous users of all smem done
        stage_tile(sb + OQ_, qG + (size_t)r0 * DHc, tid);
        stage_tile(kbuf[0], kG, tid);
        stage_tile(vbuf[0], vG, tid);
        CP_COMMIT();

        const float pm_g  = g_pm[bh * Sc + r0 + m0 + g];
        const float pm_g8 = g_pm[bh * Sc + r0 + m0 + g + 8];
        float rs0 = 0.f, rs1 = 0.f;
        float o_[64];
        #pragma unroll
        for (int i = 0; i < 64; ++i) o_[i] = 0.f;
        uint32_t qa[64];

        const uint32_t pabase0 = ((uint32_t)(m0 + lrow8) * 72 + (uint32_t)lcol8 * 8) * 2;

        for (int jt = 0; jt <= rt; ++jt) {
            const int t0 = jt * KT;
            const uint32_t okb = kbuf[jt & 1];

            CP_WAIT0();
            __syncthreads();

            // prefetch next K/V (overlaps everything below)
            if (jt < rt) {
                stage_tile(kbuf[(jt + 1) & 1], kG + (size_t)(t0 + KT) * DHc, tid);
                stage_tile(vbuf[(jt + 1) % 3], vG + (size_t)(t0 + KT) * DHc, tid);
                CP_COMMIT();
            }

            if (jt == 0) {
                uint32_t rbase = sb + OQ_ + (uint32_t)(m0 + lrow8) * 512;
                #pragma unroll
                for (int ks = 0; ks < 16; ++ks)
                    ldsm4(qa + 4 * ks, rbase + (uint32_t)(((lcol8 + 2 * ks) ^ s7) << 4));
            }

            // ---------------- QK^T (tile jt) ----------------
            float c[16];
            #pragma unroll
            for (int i = 0; i < 16; ++i) c[i] = 0.f;
            {
                #pragma unroll
                for (int ks2 = 0; ks2 < 8; ++ks2) {
                    #pragma unroll
                    for (int nt = 0; nt < 4; ++nt) {
                        uint32_t bb[4];
                        uint32_t addr = okb + (uint32_t)(32 * wn + nt * 8 + s7) * 512
                                      + (uint32_t)((((ks2 << 2) + bq8) ^ s7) << 4);
                        ldsm4(bb, addr);
                        mma16816(c + 4 * nt, qa + 8 * ks2,     bb);
                        mma16816(c + 4 * nt, qa + 8 * ks2 + 4, bb + 2);
                    }
                }
            }

            // ---------------- P @ V (tile jt-1, delayed) ----------------
            if (jt > 0) {
                uint32_t pab = pbuf[(jt - 1) & 1] + pabase0;
                uint32_t ovb = vbuf[(jt - 1) % 3];
                #pragma unroll
                for (int kst = 0; kst < 4; ++kst) {
                    uint32_t pa[4];
                    ldsm4(pa, pab + (uint32_t)kst * 32);
                    uint32_t vrow = ovb + (uint32_t)(lrow8 + kst * 16) * 512;
                    #pragma unroll
                    for (int ntp = 0; ntp < 8; ++ntp) {
                        uint32_t vb[4];
                        ldsm4t(vb, vrow + (uint32_t)(((wn * 16 + ntp * 2 + lcol8) ^ s7) << 4));
                        mma16816(o_ + 4 * (2 * ntp),     pa, vb);
                        mma16816(o_ + 4 * (2 * ntp + 1), pa, vb + 2);
                    }
                }
            }

            // ---------------- epilogue (tile jt): scale/mask/pack P ----------------
            {
                char* psb = smb + (pbuf[jt & 1] - sb);
                float ag  = __expf(sct[jt] - pm_g);
                float ag8 = __expf(sct[jt] - pm_g8);
                bool diag = (jt == rt);
                int rowg = r0 + m0 + g;
                #pragma unroll
                for (int nt = 0; nt < 4; ++nt) {
                    int col = t0 + 32 * wn + nt * 8 + 2 * tg;
                    float v0 = c[4*nt+0] * ag;
                    float v1 = c[4*nt+1] * ag;
                    float v2 = c[4*nt+2] * ag8;
                    float v3 = c[4*nt+3] * ag8;
                    if (diag) {
                        if (col     > rowg)     v0 = 0.f;
                        if (col + 1 > rowg)     v1 = 0.f;
                        if (col     > rowg + 8) v2 = 0.f;
                        if (col + 1 > rowg + 8) v3 = 0.f;
                    }
                    rs0 += v0 + v1;
                    rs1 += v2 + v3;
                    int cl = 32 * wn + nt * 8 + 2 * tg;
                    *(uint32_t*)(psb + ((m0 + g)     * 72 + cl) * 2) = pkh2(v0, v1);
                    *(uint32_t*)(psb + ((m0 + g + 8) * 72 + cl) * 2) = pkh2(v2, v3);
                }
            }
        } // jt

        __syncthreads();   // all warps wrote P(rt)

        // ---------------- final P @ V (tile rt) ----------------
        {
            uint32_t pab = pbuf[rt & 1] + pabase0;
            uint32_t ovb = vbuf[rt % 3];
            #pragma unroll
            for (int kst = 0; kst < 4; ++kst) {
                uint32_t pa[4];
                ldsm4(pa, pab + (uint32_t)kst * 32);
                uint32_t vrow = ovb + (uint32_t)(lrow8 + kst * 16) * 512;
                #pragma unroll
                for (int ntp = 0; ntp < 8; ++ntp) {
                    uint32_t vb[4];
                    ldsm4t(vb, vrow + (uint32_t)(((wn * 16 + ntp * 2 + lcol8) ^ s7) << 4));
                    mma16816(o_ + 4 * (2 * ntp),     pa, vb);
                    mma16816(o_ + 4 * (2 * ntp + 1), pa, vb + 2);
                }
            }
        }

        // ---------------- rowsum reduce + normalizer ----------------
        rs0 += __shfl_xor_sync(0xffffffffu, rs0, 1);
        rs0 += __shfl_xor_sync(0xffffffffu, rs0, 2);
        rs1 += __shfl_xor_sync(0xffffffffu, rs1, 1);
        rs1 += __shfl_xor_sync(0xffffffffu, rs1, 2);
        if (tg == 0) {
            rsA[wn * 64 + m0 + g]     = rs0;
            rsA[wn * 64 + m0 + g + 8] = rs1;
        }
        __syncthreads();
        if (tid < 64) {
            float s = rsA[tid] + rsA[64 + tid];
            float nrm = fmaxf(fabsf(s), __expf(-g_mld[bh * Sc + r0 + tid])) + 1e-8f;
            sinv[tid] = 1.f / nrm;
        }
        __syncthreads();

        // ---------------- O -> H staging (f32, stride 260) ----------------
        {
            float* H = (float*)smb;
            float ivg  = sinv[m0 + g];
            float ivg8 = sinv[m0 + g + 8];
            #pragma unroll
            for (int nt = 0; nt < 16; ++nt) {
                int col = wn * 128 + nt * 8 + 2 * tg;
                H[(m0 + g)     * 260 + col]     = o_[4*nt+0] * ivg;
                H[(m0 + g)     * 260 + col + 1] = o_[4*nt+1] * ivg;
                H[(m0 + g + 8) * 260 + col]     = o_[4*nt+2] * ivg8;
                H[(m0 + g + 8) * 260 + col + 1] = o_[4*nt+3] * ivg8;
            }
        }
        __syncthreads();

        // ---------------- LayerNorm + affine + store ----------------
        {
            const float* H = (const float*)smb;
            int r  = tid >> 2;
            int qd = tid & 3;
            const float* hrow = H + r * 260 + qd * 64;
            float s1 = 0.f;
            #pragma unroll
            for (int i = 0; i < 16; ++i) {
                float4 x = *(const float4*)(hrow + i * 4);
                s1 += x.x + x.y + x.z + x.w;
            }
            s1 += __shfl_xor_sync(0xffffffffu, s1, 1);
            s1 += __shfl_xor_sync(0xffffffffu, s1, 2);
            float mean = s1 * (1.f / 256.f);
            float s2 = 0.f;
            #pragma unroll
            for (int i = 0; i < 16; ++i) {
                float4 x = *(const float4*)(hrow + i * 4);
                float d0 = x.x - mean, d1 = x.y - mean, d2 = x.z - mean, d3 = x.w - mean;
                s2 += d0*d0 + d1*d1 + d2*d2 + d3*d3;
            }
            s2 += __shfl_xor_sync(0xffffffffu, s2, 1);
            s2 += __shfl_xor_sync(0xffffffffu, s2, 2);
            float rstd = rsqrtf(s2 * (1.f / 256.f) + 1e-5f);

            float* dst = out + ((size_t)b * Sc + r0 + r) * Ec + h * DHc + qd * 64;
            const float* ow = out_w + h * DHc + qd * 64;
            #pragma unroll
            for (int i = 0; i < 16; ++i) {
                float4 x = *(const float4*)(hrow + i * 4);
                float4 w = *(const float4*)(ow + i * 4);
                float4 y;
                y.x = (x.x - mean) * rstd * (1.f + w.x);
                y.y = (x.y - mean) * rstd * (1.f + w.y);
                y.z = (x.z - mean) * rstd * (1.f + w.z);
                y.w = (x.w - mean) * rstd * (1.f + w.w);
                *(float4*)(dst + i * 4) = y;
            }
        }
        __syncthreads();
    } // which
}

// ---------------------------------------------------------------------------
extern "C" void kernel_launch(void* const* d_in, const int* in_sizes, int n_in,
                              void* d_out, int out_size)
{
    const float* q   = (const float*)d_in[0];
    const float* k   = (const float*)d_in[1];
    const float* v   = (const float*)d_in[2];
    const float* igw = (const float*)d_in[3];
    const float* igb = (const float*)d_in[4];
    const float* fgw = (const float*)d_in[5];
    const float* fgb = (const float*)d_in[6];
    const float* ow  = (const float*)d_in[7];
    float* out = (float*)d_out;

    cudaFuncSetAttribute(attn_kernel, cudaFuncAttributeMaxDynamicSharedMemorySize, SMEM_BYTES);
    cudaFuncSetAttribute(gates_kernel, cudaFuncAttributeMaxDynamicSharedMemorySize, GATES_SMEM);

    gates_kernel<<<(Bc * Sc) / 32, 256, GATES_SMEM>>>(q, k, v, igw, igb, fgw, fgb);
    scan_kernel<<<BH, 1024>>>();
    prep_qkv<<<Bc * Sc, 256>>>(q, k, v);
    attn_kernel<<<BH * 16, 256, SMEM_BYTES>>>(ow, out);
}

// round 7
// speedup vs baseline: 9.7482x; 1.0954x over previous
#include <cuda_runtime.h>
#include <cuda_fp16.h>
#include <math.h>
#include <stdint.h>

#define Bc 2
#define Sc 2048
#define Ec 1024
#define NHc 4
#define DHc 256
#define BH  8
#define KT  64
#define NRT 32

// ------------------------- device scratch -------------------------
__device__ float g_ig [BH*Sc];
__device__ float g_lsf[BH*Sc];
__device__ float g_m  [BH*Sc];
__device__ float g_pm [BH*Sc];
__device__ float g_mld[BH*Sc];
__device__ float g_ct [BH*NRT];
__device__ __half g_qh[(size_t)BH*Sc*DHc];
__device__ __half g_kh[(size_t)BH*Sc*DHc];
__device__ __half g_vh[(size_t)BH*Sc*DHc];

// ------------------------- helpers -------------------------
__device__ __forceinline__ uint32_t smem_u32(const void* p) {
    uint32_t a;
    asm("{ .reg .u64 t; cvta.to.shared.u64 t, %1; cvt.u32.u64 %0, t; }" : "=r"(a) : "l"(p));
    return a;
}
__device__ __forceinline__ void ldsm4(uint32_t* r, uint32_t a) {
    asm volatile("ldmatrix.sync.aligned.m8n8.x4.shared.b16 {%0,%1,%2,%3}, [%4];"
        : "=r"(r[0]), "=r"(r[1]), "=r"(r[2]), "=r"(r[3]) : "r"(a));
}
__device__ __forceinline__ void ldsm4t(uint32_t* r, uint32_t a) {
    asm volatile("ldmatrix.sync.aligned.m8n8.x4.trans.shared.b16 {%0,%1,%2,%3}, [%4];"
        : "=r"(r[0]), "=r"(r[1]), "=r"(r[2]), "=r"(r[3]) : "r"(a));
}
__device__ __forceinline__ void mma16816(float* c, const uint32_t* a, const uint32_t* b) {
    asm volatile("mma.sync.aligned.m16n8k16.row.col.f32.f16.f16.f32 "
        "{%0,%1,%2,%3}, {%4,%5,%6,%7}, {%8,%9}, {%0,%1,%2,%3};"
        : "+f"(c[0]), "+f"(c[1]), "+f"(c[2]), "+f"(c[3])
        : "r"(a[0]), "r"(a[1]), "r"(a[2]), "r"(a[3]), "r"(b[0]), "r"(b[1]));
}
__device__ __forceinline__ uint32_t pkh2(float lo, float hi) {
    uint32_t r; asm("cvt.rn.f16x2.f32 %0, %1, %2;" : "=r"(r) : "f"(hi), "f"(lo)); return r;
}
__device__ __forceinline__ void cpa16(uint32_t s, const void* g) {
    asm volatile("cp.async.cg.shared.global [%0], [%1], 16;" :: "r"(s), "l"(g));
}
#define CP_COMMIT() asm volatile("cp.async.commit_group;" ::: "memory")
#define CP_WAIT0()  asm volatile("cp.async.wait_group 0;" ::: "memory")

// stage a 64x256-half tile into swizzled smem (512B rows, chunk^(row&7))
__device__ __forceinline__ void stage_tile(uint32_t dst, const __half* src, int tid) {
    #pragma unroll
    for (int it = 0; it < 8; ++it) {
        int lin = tid + it * 256;
        int row = lin >> 5, d8 = lin & 31;
        uint32_t o = dst + row * 512 + (uint32_t)((d8 ^ (row & 7)) << 4);
        cpa16(o, src + (size_t)row * 256 + d8 * 8);
    }
}

// ---------------------------------------------------------------------------
// gates: smem-cached weights; ALSO writes q,v as fp16 (head-split) on the fly
// ---------------------------------------------------------------------------
#define GATES_SMEM (24576 * 4)
__global__ __launch_bounds__(256) void gates_kernel(
    const float* __restrict__ q, const float* __restrict__ k, const float* __restrict__ v,
    const float* __restrict__ igw, const float* __restrict__ igb,
    const float* __restrict__ fgw, const float* __restrict__ fgb)
{
    extern __shared__ float ws[];   // [0:12288) igw, [12288:24576) fgw
    int tid  = threadIdx.x;
    int warp = tid >> 5;
    int lane = tid & 31;

    #pragma unroll
    for (int it = 0; it < 24; ++it) {
        int idx = tid + it * 256;   // float4 index 0..6143
        float4 val = (idx < 3072) ? ((const float4*)igw)[idx]
                                  : ((const float4*)fgw)[idx - 3072];
        ((float4*)ws)[idx] = val;
    }
    __syncthreads();

    int row0 = blockIdx.x * 32 + warp * 4;
    float acc[4][8];
    #pragma unroll
    for (int r = 0; r < 4; ++r)
        #pragma unroll
        for (int c = 0; c < 8; ++c) acc[r][c] = 0.f;

    #pragma unroll
    for (int part = 0; part < 3; ++part) {
        const float* bp = (part == 0) ? q : (part == 1) ? k : v;
        #pragma unroll
        for (int it = 0; it < 8; ++it) {
            int f  = it * 128 + lane * 4;
            int wf = part * 1024 + f;
            float4 wi[4], wg[4];
            #pragma unroll
            for (int h = 0; h < 4; ++h) {
                wi[h] = *(const float4*)(ws + h * 3072 + wf);
                wg[h] = *(const float4*)(ws + 12288 + h * 3072 + wf);
            }
            #pragma unroll
            for (int r = 0; r < 4; ++r) {
                int row = row0 + r;
                float4 x = *(const float4*)(bp + (size_t)row * Ec + f);
                #pragma unroll
                for (int h = 0; h < 4; ++h) {
                    acc[r][h]     += x.x*wi[h].x + x.y*wi[h].y + x.z*wi[h].z + x.w*wi[h].w;
                    acc[r][h + 4] += x.x*wg[h].x + x.y*wg[h].y + x.z*wg[h].z + x.w*wg[h].w;
                }
                if (part != 1) {   // q or v: write fp16 head-split copy
                    int bb = row >> 11, s = row & (Sc - 1);
                    int hh = f >> 8, dd = f & 255;
                    __half* dst = (part == 0 ? g_qh : g_vh)
                                + ((size_t)(bb * NHc + hh) * Sc + s) * DHc + dd;
                    ((__half2*)dst)[0] = __floats2half2_rn(x.x, x.y);
                    ((__half2*)dst)[1] = __floats2half2_rn(x.z, x.w);
                }
            }
        }
    }
    #pragma unroll
    for (int o = 16; o; o >>= 1)
        #pragma unroll
        for (int r = 0; r < 4; ++r)
            #pragma unroll
            for (int c = 0; c < 8; ++c)
                acc[r][c] += __shfl_xor_sync(0xffffffffu, acc[r][c], o);

    int r = lane >> 3, c = lane & 7;
    float val = 0.f;
    #pragma unroll
    for (int rr = 0; rr < 4; ++rr)
        #pragma unroll
        for (int cc = 0; cc < 8; ++cc)
            if (rr == r && cc == c) val = acc[rr][cc];

    int row = row0 + r;
    int b = row >> 11;
    int s = row & (Sc - 1);
    if (c < 4) {
        g_ig[(b * NHc + c) * Sc + s] = val + igb[c];
    } else {
        int h = c - 4;
        float fgv = val + fgb[h];
        float lsf = fminf(fgv, 0.f) - log1pf(expf(-fabsf(fgv)));
        g_lsf[(b * NHc + h) * Sc + s] = lsf;
    }
}

// ---------------------------------------------------------------------------
// scan: cumsum, m, per-64-tile max, prefix-max, mld
// ---------------------------------------------------------------------------
__global__ __launch_bounds__(1024) void scan_kernel()
{
    __shared__ float s_a[2048];
    __shared__ float s_b[2048];
    __shared__ float s_cs[2048];

    int bh = blockIdx.x;
    int t  = threadIdx.x;
    const int base = bh * Sc;

    s_a[t]        = g_lsf[base + t];
    s_a[t + 1024] = g_lsf[base + t + 1024];
    __syncthreads();

    float* src = s_a; float* dst = s_b;
    for (int off = 1; off < 2048; off <<= 1) {
        #pragma unroll
        for (int u = 0; u < 2; ++u) {
            int i = t + (u << 10);
            float val = src[i];
            if (i >= off) val += src[i - off];
            dst[i] = val;
        }
        __syncthreads();
        float* tmp = src; src = dst; dst = tmp;
    }
    s_cs[t]        = src[t];
    s_cs[t + 1024] = src[t + 1024];
    __syncthreads();

    #pragma unroll
    for (int u = 0; u < 2; ++u) {
        int i = t + (u << 10);
        float m = g_ig[base + i] - (i > 0 ? s_cs[i - 1] : 0.f);
        g_m[base + i] = m;
        s_a[i] = m;
    }
    __syncthreads();

    if (t < NRT) {
        float mx = -1e30f;
        #pragma unroll 4
        for (int i = 0; i < KT; ++i) mx = fmaxf(mx, s_a[t * KT + i]);
        g_ct[bh * NRT + t] = mx;
    }
    __syncthreads();

    src = s_a; dst = s_b;
    for (int off = 1; off < 2048; off <<= 1) {
        #pragma unroll
        for (int u = 0; u < 2; ++u) {
            int i = t + (u << 10);
            float val = src[i];
            if (i >= off) val = fmaxf(val, src[i - off]);
            dst[i] = val;
        }
        __syncthreads();
        float* tmp = src; src = dst; dst = tmp;
    }
    #pragma unroll
    for (int u = 0; u < 2; ++u) {
        int i = t + (u << 10);
        g_pm[base + i]  = src[i];
        g_mld[base + i] = s_cs[i] + src[i];
    }
}

// ---------------------------------------------------------------------------
// prep_k: k -> fp16 scaled by exp(m - ct)/16, head-split layout
// ---------------------------------------------------------------------------
__global__ __launch_bounds__(256) void prep_k(const float* __restrict__ k)
{
    int row = blockIdx.x;           // b*S + s
    int b = row >> 11, s = row & 2047;
    int t = threadIdx.x;
    int h = t >> 6;
    int d = (t & 63) * 4;
    int bh = b * NHc + h;
    float sc = __expf(g_m[bh * Sc + s] - g_ct[bh * NRT + (s >> 6)]) * 0.0625f;
    float4 kv = *(const float4*)(k + (size_t)row * Ec + t * 4);
    size_t o = ((size_t)bh * Sc + s) * DHc + d;
    __half2* ko = (__half2*)(g_kh + o);
    ko[0] = __floats2half2_rn(kv.x * sc, kv.y * sc);
    ko[1] = __floats2half2_rn(kv.z * sc, kv.w * sc);
}

// ---------------------------------------------------------------------------
// attention: HMMA, INTERLEAVED QK(jt) + PV(jt-1), K x2 / V x3 / P x2 buffers
// ---------------------------------------------------------------------------
#define OQ_  0
#define OK0  32768
#define OK1  65536
#define OV0  98304
#define OV1  131072
#define OV2  163840
#define OPS0 196608
#define OPS1 205824
#define ORS  215040
#define OINV 215552
#define OCT  215808
#define SMEM_BYTES 215936

__global__ __launch_bounds__(256, 1) void attn_kernel(
    const float* __restrict__ out_w, float* __restrict__ out)
{
    extern __shared__ char smb[];
    const uint32_t sb = smem_u32(smb);

    float* rsA  = (float*)(smb + ORS);
    float* sinv = (float*)(smb + OINV);
    float* sct  = (float*)(smb + OCT);

    const int tid  = threadIdx.x;
    const int wid  = tid >> 5;
    const int lane = tid & 31;
    const int bh   = blockIdx.x >> 4;
    const int pair = blockIdx.x & 15;
    const int b = bh >> 2, h = bh & 3;

    const int wm = wid & 3;        // m-tile (16 rows)
    const int wn = wid >> 2;       // key half (QK) / dh half (PV)
    const int m0 = wm * 16;
    const int g  = lane >> 2;
    const int tg = lane & 3;
    const int s7 = lane & 7;       // swizzle key

    if (tid < NRT) sct[tid] = g_ct[bh * NRT + tid];

    const __half* qG = g_qh + (size_t)bh * Sc * DHc;
    const __half* kG = g_kh + (size_t)bh * Sc * DHc;
    const __half* vG = g_vh + (size_t)bh * Sc * DHc;

    const int lrow8 = (lane & 7) + 8 * ((lane >> 3) & 1);  // A/V row pattern
    const int lcol8 = (lane >> 4);                          // A/V col-quarter
    const int bq8   = (lane >> 3);                          // K dh quarter

    const uint32_t vbuf[3] = { sb + OV0, sb + OV1, sb + OV2 };
    const uint32_t kbuf[2] = { sb + OK0, sb + OK1 };
    const uint32_t pbuf[2] = { sb + OPS0, sb + OPS1 };

    for (int which = 0; which < 2; ++which) {
        const int rt = which ? (31 - pair) : pair;
        const int r0 = rt * KT;

        __syncthreads();   // previous users of all smem done
        stage_tile(sb + OQ_, qG + (size_t)r0 * DHc, tid);
        stage_tile(kbuf[0], kG, tid);
        stage_tile(vbuf[0], vG, tid);
        CP_COMMIT();

        const float pm_g  = g_pm[bh * Sc + r0 + m0 + g];
        const float pm_g8 = g_pm[bh * Sc + r0 + m0 + g + 8];
        float rs0 = 0.f, rs1 = 0.f;
        float o_[64];
        #pragma unroll
        for (int i = 0; i < 64; ++i) o_[i] = 0.f;
        uint32_t qa[64];

        const uint32_t pabase0 = ((uint32_t)(m0 + lrow8) * 72 + (uint32_t)lcol8 * 8) * 2;

        for (int jt = 0; jt <= rt; ++jt) {
            const int t0 = jt * KT;
            const uint32_t okb = kbuf[jt & 1];

            CP_WAIT0();
            __syncthreads();

            // prefetch next K/V (overlaps everything below)
            if (jt < rt) {
                stage_tile(kbuf[(jt + 1) & 1], kG + (size_t)(t0 + KT) * DHc, tid);
                stage_tile(vbuf[(jt + 1) % 3], vG + (size_t)(t0 + KT) * DHc, tid);
                CP_COMMIT();
            }

            if (jt == 0) {
                uint32_t rbase = sb + OQ_ + (uint32_t)(m0 + lrow8) * 512;
                #pragma unroll
                for (int ks = 0; ks < 16; ++ks)
                    ldsm4(qa + 4 * ks, rbase + (uint32_t)(((lcol8 + 2 * ks) ^ s7) << 4));
            }

            // ======= INTERLEAVED: QK(jt) + PV(jt-1) — two independent chains =======
            float c[16];
            #pragma unroll
            for (int i = 0; i < 16; ++i) c[i] = 0.f;

            const bool havePV = (jt > 0);
            const uint32_t pab = pbuf[(jt + 1) & 1] + pabase0;  // (jt-1)&1
            const uint32_t ovb = vbuf[(jt + 2) % 3];            // (jt-1)%3
            uint32_t pa[4];

            #pragma unroll
            for (int ks2 = 0; ks2 < 8; ++ks2) {
                // ---- QK quarter: 4 ldsm + 8 mma ----
                #pragma unroll
                for (int nt = 0; nt < 4; ++nt) {
                    uint32_t bb[4];
                    uint32_t addr = okb + (uint32_t)(32 * wn + nt * 8 + s7) * 512
                                  + (uint32_t)((((ks2 << 2) + bq8) ^ s7) << 4);
                    ldsm4(bb, addr);
                    mma16816(c + 4 * nt, qa + 8 * ks2,     bb);
                    mma16816(c + 4 * nt, qa + 8 * ks2 + 4, bb + 2);
                }
                // ---- PV(jt-1) chunk: (P-ldsm every other step) + 4 V-ldsm + 8 mma ----
                if (havePV) {
                    int kst = ks2 >> 1;
                    int hh  = ks2 & 1;
                    if (hh == 0) ldsm4(pa, pab + (uint32_t)kst * 32);
                    uint32_t vrow = ovb + (uint32_t)(lrow8 + kst * 16) * 512;
                    #pragma unroll
                    for (int nn = 0; nn < 4; ++nn) {
                        int ntp = hh * 4 + nn;
                        uint32_t vb[4];
                        ldsm4t(vb, vrow + (uint32_t)(((wn * 16 + ntp * 2 + lcol8) ^ s7) << 4));
                        mma16816(o_ + 4 * (2 * ntp),     pa, vb);
                        mma16816(o_ + 4 * (2 * ntp + 1), pa, vb + 2);
                    }
                }
            }

            // ---------------- epilogue (tile jt): scale/mask/pack P ----------------
            {
                char* psb = smb + (pbuf[jt & 1] - sb);
                float ag  = __expf(sct[jt] - pm_g);
                float ag8 = __expf(sct[jt] - pm_g8);
                bool diag = (jt == rt);
                int rowg = r0 + m0 + g;
                #pragma unroll
                for (int nt = 0; nt < 4; ++nt) {
                    int col = t0 + 32 * wn + nt * 8 + 2 * tg;
                    float v0 = c[4*nt+0] * ag;
                    float v1 = c[4*nt+1] * ag;
                    float v2 = c[4*nt+2] * ag8;
                    float v3 = c[4*nt+3] * ag8;
                    if (diag) {
                        if (col     > rowg)     v0 = 0.f;
                        if (col + 1 > rowg)     v1 = 0.f;
                        if (col     > rowg + 8) v2 = 0.f;
                        if (col + 1 > rowg + 8) v3 = 0.f;
                    }
                    rs0 += v0 + v1;
                    rs1 += v2 + v3;
                    int cl = 32 * wn + nt * 8 + 2 * tg;
                    *(uint32_t*)(psb + ((m0 + g)     * 72 + cl) * 2) = pkh2(v0, v1);
                    *(uint32_t*)(psb + ((m0 + g + 8) * 72 + cl) * 2) = pkh2(v2, v3);
                }
            }
        } // jt

        __syncthreads();   // all warps wrote P(rt)

        // ---------------- final P @ V (tile rt) ----------------
        {
            uint32_t pab = pbuf[rt & 1] + pabase0;
            uint32_t ovb = vbuf[rt % 3];
            #pragma unroll
            for (int kst = 0; kst < 4; ++kst) {
                uint32_t pa[4];
                ldsm4(pa, pab + (uint32_t)kst * 32);
                uint32_t vrow = ovb + (uint32_t)(lrow8 + kst * 16) * 512;
                #pragma unroll
                for (int ntp = 0; ntp < 8; ++ntp) {
                    uint32_t vb[4];
                    ldsm4t(vb, vrow + (uint32_t)(((wn * 16 + ntp * 2 + lcol8) ^ s7) << 4));
                    mma16816(o_ + 4 * (2 * ntp),     pa, vb);
                    mma16816(o_ + 4 * (2 * ntp + 1), pa, vb + 2);
                }
            }
        }

        // ---------------- rowsum reduce + normalizer ----------------
        rs0 += __shfl_xor_sync(0xffffffffu, rs0, 1);
        rs0 += __shfl_xor_sync(0xffffffffu, rs0, 2);
        rs1 += __shfl_xor_sync(0xffffffffu, rs1, 1);
        rs1 += __shfl_xor_sync(0xffffffffu, rs1, 2);
        if (tg == 0) {
            rsA[wn * 64 + m0 + g]     = rs0;
            rsA[wn * 64 + m0 + g + 8] = rs1;
        }
        __syncthreads();
        if (tid < 64) {
            float s = rsA[tid] + rsA[64 + tid];
            float nrm = fmaxf(fabsf(s), __expf(-g_mld[bh * Sc + r0 + tid])) + 1e-8f;
            sinv[tid] = 1.f / nrm;
        }
        __syncthreads();

        // ---------------- O -> H staging (f32, stride 260) ----------------
        {
            float* H = (float*)smb;
            float ivg  = sinv[m0 + g];
            float ivg8 = sinv[m0 + g + 8];
            #pragma unroll
            for (int nt = 0; nt < 16; ++nt) {
                int col = wn * 128 + nt * 8 + 2 * tg;
                H[(m0 + g)     * 260 + col]     = o_[4*nt+0] * ivg;
                H[(m0 + g)     * 260 + col + 1] = o_[4*nt+1] * ivg;
                H[(m0 + g + 8) * 260 + col]     = o_[4*nt+2] * ivg8;
                H[(m0 + g + 8) * 260 + col + 1] = o_[4*nt+3] * ivg8;
            }
        }
        __syncthreads();

        // ---------------- LayerNorm + affine + store ----------------
        {
            const float* H = (const float*)smb;
            int r  = tid >> 2;
            int qd = tid & 3;
            const float* hrow = H + r * 260 + qd * 64;
            float s1 = 0.f;
            #pragma unroll
            for (int i = 0; i < 16; ++i) {
                float4 x = *(const float4*)(hrow + i * 4);
                s1 += x.x + x.y + x.z + x.w;
            }
            s1 += __shfl_xor_sync(0xffffffffu, s1, 1);
            s1 += __shfl_xor_sync(0xffffffffu, s1, 2);
            float mean = s1 * (1.f / 256.f);
            float s2 = 0.f;
            #pragma unroll
            for (int i = 0; i < 16; ++i) {
                float4 x = *(const float4*)(hrow + i * 4);
                float d0 = x.x - mean, d1 = x.y - mean, d2 = x.z - mean, d3 = x.w - mean;
                s2 += d0*d0 + d1*d1 + d2*d2 + d3*d3;
            }
            s2 += __shfl_xor_sync(0xffffffffu, s2, 1);
            s2 += __shfl_xor_sync(0xffffffffu, s2, 2);
            float rstd = rsqrtf(s2 * (1.f / 256.f) + 1e-5f);

            float* dst = out + ((size_t)b * Sc + r0 + r) * Ec + h * DHc + qd * 64;
            const float* ow = out_w + h * DHc + qd * 64;
            #pragma unroll
            for (int i = 0; i < 16; ++i) {
                float4 x = *(const float4*)(hrow + i * 4);
                float4 w = *(const float4*)(ow + i * 4);
                float4 y;
                y.x = (x.x - mean) * rstd * (1.f + w.x);
                y.y = (x.y - mean) * rstd * (1.f + w.y);
                y.z = (x.z - mean) * rstd * (1.f + w.z);
                y.w = (x.w - mean) * rstd * (1.f + w.w);
                *(float4*)(dst + i * 4) = y;
            }
        }
        __syncthreads();
    } // which
}

// ---------------------------------------------------------------------------
extern "C" void kernel_launch(void* const* d_in, const int* in_sizes, int n_in,
                              void* d_out, int out_size)
{
    const float* q   = (const float*)d_in[0];
    const float* k   = (const float*)d_in[1];
    const float* v   = (const float*)d_in[2];
    const float* igw = (const float*)d_in[3];
    const float* igb = (const float*)d_in[4];
    const float* fgw = (const float*)d_in[5];
    const float* fgb = (const float*)d_in[6];
    const float* ow  = (const float*)d_in[7];
    float* out = (float*)d_out;

    cudaFuncSetAttribute(attn_kernel, cudaFuncAttributeMaxDynamicSharedMemorySize, SMEM_BYTES);
    cudaFuncSetAttribute(gates_kernel, cudaFuncAttributeMaxDynamicSharedMemorySize, GATES_SMEM);

    gates_kernel<<<(Bc * Sc) / 32, 256, GATES_SMEM>>>(q, k, v, igw, igb, fgw, fgb);
    scan_kernel<<<BH, 1024>>>();
    prep_k<<<Bc * Sc, 256>>>(k);
    attn_kernel<<<BH * 16, 256, SMEM_BYTES>>>(ow, out);
}